// round 5
// baseline (speedup 1.0000x reference)
#include <cuda_runtime.h>
#include <cuda_bf16.h>
#include <cstdint>

// Problem constants
#define NN 50000
#define EE 800000
#define GG 2048
#define HH 256
#define KPAD 64   // 59 padded to 64

// ---------------- device scratch (no allocation allowed) ----------------
__device__ float g_bufA[NN * HH];     // 51.2 MB
__device__ float g_bufB[NN * HH];     // 51.2 MB
__device__ float g_xpad[NN * KPAD];   // 12.8 MB
__device__ float g_wpad[HH * KPAD];
__device__ int   g_deg[NN];
__device__ int   g_off[NN + 1];
__device__ int   g_cur[NN];
__device__ int   g_srcs[EE];
__device__ float g_coef[EE];
__device__ float g_dinv[NN];
__device__ int   g_gstart[GG + 1];
__device__ float g_gA[GG * HH];
__device__ float g_gB[GG * HH];

// ---------------- small helpers ----------------
__device__ __forceinline__ unsigned long long dup2(float v) {
    unsigned long long r;
    asm("mov.b64 %0, {%1, %1};" : "=l"(r) : "f"(v));
    return r;
}
__device__ __forceinline__ void fma2(unsigned long long& d,
                                     unsigned long long a,
                                     unsigned long long b) {
    asm("fma.rn.f32x2 %0, %1, %2, %0;" : "+l"(d) : "l"(a), "l"(b));
}
__device__ __forceinline__ float2 unpack2(unsigned long long v) {
    float2 f;
    asm("mov.b64 {%0, %1}, %2;" : "=f"(f.x), "=f"(f.y) : "l"(v));
    return f;
}
__device__ __forceinline__ float4 fma4(float c, float4 v, float4 a) {
    a.x += c * v.x; a.y += c * v.y; a.z += c * v.z; a.w += c * v.w;
    return a;
}
__device__ __forceinline__ float4 add4(float4 a, float4 b) {
    a.x += b.x; a.y += b.y; a.z += b.z; a.w += b.w; return a;
}

// ---------------- CSR construction ----------------
__global__ void k_zero_deg() {
    int i = blockIdx.x * blockDim.x + threadIdx.x;
    if (i < NN) g_deg[i] = 0;
}
__global__ void k_hist(const int* __restrict__ ei) {
    int e = blockIdx.x * blockDim.x + threadIdx.x;
    if (e < EE) atomicAdd(&g_deg[ei[EE + e]], 1);
}
__global__ void k_dinv() {
    int i = blockIdx.x * blockDim.x + threadIdx.x;
    if (i < NN) g_dinv[i] = rsqrtf((float)g_deg[i] + 1.0f);
}
// single-block exclusive scan over g_deg -> g_off, g_cur
__global__ void k_scan() {
    __shared__ int sh[1024];
    __shared__ int s_carry;
    int tid = threadIdx.x;
    if (tid == 0) s_carry = 0;
    __syncthreads();
    for (int base = 0; base < NN; base += 1024) {
        int idx = base + tid;
        int v = (idx < NN) ? g_deg[idx] : 0;
        sh[tid] = v;
        __syncthreads();
        for (int d = 1; d < 1024; d <<= 1) {
            int t = (tid >= d) ? sh[tid - d] : 0;
            __syncthreads();
            sh[tid] += t;
            __syncthreads();
        }
        int carry = s_carry;
        int excl = carry + sh[tid] - v;
        if (idx < NN) { g_off[idx] = excl; g_cur[idx] = excl; }
        __syncthreads();
        if (tid == 1023) s_carry = carry + sh[1023];
        __syncthreads();
    }
    if (tid == 0) g_off[NN] = s_carry;
}
__global__ void k_scatter(const int* __restrict__ ei) {
    int e = blockIdx.x * blockDim.x + threadIdx.x;
    if (e >= EE) return;
    int s = ei[e];
    int d = ei[EE + e];
    int pos = atomicAdd(&g_cur[d], 1);
    g_srcs[pos] = s;
    g_coef[pos] = g_dinv[s];
}

// ---------------- input padding ----------------
__global__ void k_pad_x(const float* __restrict__ x) {
    int idx = blockIdx.x * blockDim.x + threadIdx.x;
    if (idx >= NN * KPAD) return;
    int i = idx / KPAD, c = idx % KPAD;
    g_xpad[idx] = (c < 59) ? x[i * 59 + c] : 0.0f;
}
__global__ void k_pad_w(const float* __restrict__ w) {
    int idx = blockIdx.x * blockDim.x + threadIdx.x;
    if (idx >= HH * KPAD) return;
    int i = idx / KPAD, c = idx % KPAD;
    g_wpad[idx] = (c < 59) ? w[i * 59 + c] : 0.0f;
}

// ---------------- SGEMM: C[M,256] = A[M,K] @ W[256,K]^T (+bias)(+relu) ----
// 128x128 tile, BK=8, 256 threads, 8x8 per thread with f32x2 packed FMA.
__global__ void __launch_bounds__(256) sgemm_kernel(
    const float* __restrict__ A, const float* __restrict__ W,
    const float* __restrict__ bias, float* __restrict__ C,
    int M, int K, int flags) {
    __shared__ __align__(16) float As[8][128];
    __shared__ __align__(16) float Ws[8][128];
    const int m0 = blockIdx.x * 128;
    const int n0 = blockIdx.y * 128;
    const int tid = threadIdx.x;
    const int tx = tid & 15;       // 0..15 -> 8 output cols each
    const int ty = tid >> 4;       // 0..15 -> 8 output rows each
    const int lrow = tid >> 1;     // 0..127
    const int lc4 = (tid & 1) * 4; // 0 or 4

    unsigned long long acc[4][8];
#pragma unroll
    for (int p = 0; p < 4; ++p)
#pragma unroll
        for (int j = 0; j < 8; ++j) acc[p][j] = 0ull;

    for (int k0 = 0; k0 < K; k0 += 8) {
        // load A tile (transposed to As[k][m]) — guard rows
        float4 av = make_float4(0.f, 0.f, 0.f, 0.f);
        int am = m0 + lrow;
        if (am < M) av = *(const float4*)(A + (size_t)am * K + k0 + lc4);
        As[lc4 + 0][lrow] = av.x;
        As[lc4 + 1][lrow] = av.y;
        As[lc4 + 2][lrow] = av.z;
        As[lc4 + 3][lrow] = av.w;
        // load W tile (transposed to Ws[k][n]); n0+lrow < 256 always
        float4 wv = *(const float4*)(W + (size_t)(n0 + lrow) * K + k0 + lc4);
        Ws[lc4 + 0][lrow] = wv.x;
        Ws[lc4 + 1][lrow] = wv.y;
        Ws[lc4 + 2][lrow] = wv.z;
        Ws[lc4 + 3][lrow] = wv.w;
        __syncthreads();
#pragma unroll
        for (int kk = 0; kk < 8; ++kk) {
            // 8 A values (rows) as 4 packed pairs — direct 16B loads
            ulonglong2 a01 = *(const ulonglong2*)&As[kk][ty * 8];
            ulonglong2 a23 = *(const ulonglong2*)&As[kk][ty * 8 + 4];
            unsigned long long ap[4] = {a01.x, a01.y, a23.x, a23.y};
            float4 b0 = *(const float4*)&Ws[kk][tx * 8];
            float4 b1 = *(const float4*)&Ws[kk][tx * 8 + 4];
            float bf[8] = {b0.x, b0.y, b0.z, b0.w, b1.x, b1.y, b1.z, b1.w};
#pragma unroll
            for (int j = 0; j < 8; ++j) {
                unsigned long long bd = dup2(bf[j]);
#pragma unroll
                for (int p = 0; p < 4; ++p) fma2(acc[p][j], ap[p], bd);
            }
        }
        __syncthreads();
    }

    // epilogue
    const bool do_bias = (flags & 1) != 0;
    const bool do_relu = (flags & 2) != 0;
    float bv[8];
#pragma unroll
    for (int j = 0; j < 8; ++j) bv[j] = 0.0f;
    if (do_bias) {
        float4 bb0 = *(const float4*)&bias[n0 + tx * 8];
        float4 bb1 = *(const float4*)&bias[n0 + tx * 8 + 4];
        bv[0] = bb0.x; bv[1] = bb0.y; bv[2] = bb0.z; bv[3] = bb0.w;
        bv[4] = bb1.x; bv[5] = bb1.y; bv[6] = bb1.z; bv[7] = bb1.w;
    }
#pragma unroll
    for (int p = 0; p < 4; ++p) {
        float2 r[8];
#pragma unroll
        for (int j = 0; j < 8; ++j) r[j] = unpack2(acc[p][j]);
#pragma unroll
        for (int h = 0; h < 2; ++h) {
            int m = m0 + ty * 8 + 2 * p + h;
            if (m < M) {
                float v[8];
#pragma unroll
                for (int j = 0; j < 8; ++j) {
                    float t = (h ? r[j].y : r[j].x) + bv[j];
                    if (do_relu) t = fmaxf(t, 0.0f);
                    v[j] = t;
                }
                float* crow = C + (size_t)m * 256 + n0 + tx * 8;
                *(float4*)crow = make_float4(v[0], v[1], v[2], v[3]);
                *(float4*)(crow + 4) = make_float4(v[4], v[5], v[6], v[7]);
            }
        }
    }
}

// ---------------- GCN aggregation: warp per node, gather-only ----------
__global__ void aggregate_kernel(const float* __restrict__ h2,
                                 const float* __restrict__ bias,
                                 float* __restrict__ out) {
    int warp = (blockIdx.x * blockDim.x + threadIdx.x) >> 5;
    if (warp >= NN) return;
    int lane = threadIdx.x & 31;
    float4 acc0 = make_float4(0.f, 0.f, 0.f, 0.f);
    float4 acc1 = make_float4(0.f, 0.f, 0.f, 0.f);
    int s = g_off[warp], e = g_off[warp + 1];
    int j = s;
    for (; j + 1 < e; j += 2) {
        int s0 = g_srcs[j], s1 = g_srcs[j + 1];
        float c0 = g_coef[j], c1 = g_coef[j + 1];
        const float4* r0 = (const float4*)(h2 + (size_t)s0 * 256);
        const float4* r1 = (const float4*)(h2 + (size_t)s1 * 256);
        float4 v00 = r0[lane], v01 = r0[lane + 32];
        float4 v10 = r1[lane], v11 = r1[lane + 32];
        acc0 = fma4(c0, v00, acc0);
        acc1 = fma4(c0, v01, acc1);
        acc0 = fma4(c1, v10, acc0);
        acc1 = fma4(c1, v11, acc1);
    }
    if (j < e) {
        int s0 = g_srcs[j];
        float c0 = g_coef[j];
        const float4* r0 = (const float4*)(h2 + (size_t)s0 * 256);
        acc0 = fma4(c0, r0[lane], acc0);
        acc1 = fma4(c0, r0[lane + 32], acc1);
    }
    float di = g_dinv[warp];
    float d2 = di * di;
    const float4* self = (const float4*)(h2 + (size_t)warp * 256);
    float4 s0v = self[lane], s1v = self[lane + 32];
    const float4* b = (const float4*)bias;
    float4 b0 = b[lane], b1 = b[lane + 32];
    float4 o0, o1;
    o0.x = fmaxf(acc0.x * di + d2 * s0v.x + b0.x, 0.0f);
    o0.y = fmaxf(acc0.y * di + d2 * s0v.y + b0.y, 0.0f);
    o0.z = fmaxf(acc0.z * di + d2 * s0v.z + b0.z, 0.0f);
    o0.w = fmaxf(acc0.w * di + d2 * s0v.w + b0.w, 0.0f);
    o1.x = fmaxf(acc1.x * di + d2 * s1v.x + b1.x, 0.0f);
    o1.y = fmaxf(acc1.y * di + d2 * s1v.y + b1.y, 0.0f);
    o1.z = fmaxf(acc1.z * di + d2 * s1v.z + b1.z, 0.0f);
    o1.w = fmaxf(acc1.w * di + d2 * s1v.w + b1.w, 0.0f);
    float4* orow = (float4*)(out + (size_t)warp * 256);
    orow[lane] = o0;
    orow[lane + 32] = o1;
}

// ---------------- pooling ----------------
__global__ void k_gstart(const int* __restrict__ batch) {
    int i = blockIdx.x * blockDim.x + threadIdx.x;
    if (i >= NN) return;
    int b = batch[i];
    int prev = (i == 0) ? -1 : batch[i - 1];
    for (int g = prev + 1; g <= b; ++g) g_gstart[g] = i;
    if (i == NN - 1) {
        for (int g = b + 1; g <= GG; ++g) g_gstart[g] = NN;
    }
}
__global__ void k_pool(const float* __restrict__ h, float* __restrict__ out) {
    int warp = (blockIdx.x * blockDim.x + threadIdx.x) >> 5;
    if (warp >= GG) return;
    int lane = threadIdx.x & 31;
    float4 acc0 = make_float4(0.f, 0.f, 0.f, 0.f);
    float4 acc1 = make_float4(0.f, 0.f, 0.f, 0.f);
    int s = g_gstart[warp], e = g_gstart[warp + 1];
    for (int i = s; i < e; ++i) {
        const float4* r = (const float4*)(h + (size_t)i * 256);
        acc0 = add4(acc0, r[lane]);
        acc1 = add4(acc1, r[lane + 32]);
    }
    float4* orow = (float4*)(out + (size_t)warp * 256);
    orow[lane] = acc0;
    orow[lane + 32] = acc1;
}

// ---------------- output head: 2 dots + log_softmax, warp per graph -----
__global__ void k_out(const float* __restrict__ g,
                      const float* __restrict__ out_w,
                      const float* __restrict__ out_b,
                      float* __restrict__ out) {
    int warp = (blockIdx.x * blockDim.x + threadIdx.x) >> 5;
    if (warp >= GG) return;
    int lane = threadIdx.x & 31;
    const float* row = g + (size_t)warp * 256;
    float p0 = 0.f, p1 = 0.f;
    for (int k = lane; k < 256; k += 32) {
        float v = row[k];
        p0 += v * out_w[k];
        p1 += v * out_w[256 + k];
    }
#pragma unroll
    for (int o = 16; o; o >>= 1) {
        p0 += __shfl_down_sync(0xffffffffu, p0, o);
        p1 += __shfl_down_sync(0xffffffffu, p1, o);
    }
    if (lane == 0) {
        float z0 = p0 + out_b[0];
        float z1 = p1 + out_b[1];
        float m = fmaxf(z0, z1);
        float lse = m + logf(expf(z0 - m) + expf(z1 - m));
        out[warp * 2 + 0] = z0 - lse;
        out[warp * 2 + 1] = z1 - lse;
    }
}

// ---------------- launch ----------------
extern "C" void kernel_launch(void* const* d_in, const int* in_sizes, int n_in,
                              void* d_out, int out_size) {
    const float* x       = (const float*)d_in[0];
    const int*   ei      = (const int*)d_in[1];
    const int*   batch   = (const int*)d_in[2];
    const float* W_embed = (const float*)d_in[3];
    const float* b_embed = (const float*)d_in[4];
    const float* conv_w  = (const float*)d_in[5];
    const float* conv_b  = (const float*)d_in[6];
    const float* fc_w    = (const float*)d_in[7];
    const float* fc_b    = (const float*)d_in[8];
    const float* out_w   = (const float*)d_in[9];
    const float* out_b   = (const float*)d_in[10];
    float* out = (float*)d_out;

    float *bufA, *bufB, *xpad, *wpad, *gA, *gB;
    cudaGetSymbolAddress((void**)&bufA, g_bufA);
    cudaGetSymbolAddress((void**)&bufB, g_bufB);
    cudaGetSymbolAddress((void**)&xpad, g_xpad);
    cudaGetSymbolAddress((void**)&wpad, g_wpad);
    cudaGetSymbolAddress((void**)&gA, g_gA);
    cudaGetSymbolAddress((void**)&gB, g_gB);

    const int TB = 256;
    // ---- CSR build (recomputed every launch; deterministic work) ----
    k_zero_deg<<<(NN + TB - 1) / TB, TB>>>();
    k_hist<<<(EE + TB - 1) / TB, TB>>>(ei);
    k_dinv<<<(NN + TB - 1) / TB, TB>>>();
    k_scan<<<1, 1024>>>();
    k_scatter<<<(EE + TB - 1) / TB, TB>>>(ei);

    // ---- embed: relu(x @ W_embed^T + b) via K=64 padding ----
    k_pad_x<<<(NN * KPAD + TB - 1) / TB, TB>>>(x);
    k_pad_w<<<(HH * KPAD + TB - 1) / TB, TB>>>(W_embed);
    dim3 gridN((NN + 127) / 128, 2);
    sgemm_kernel<<<gridN, 256>>>(xpad, wpad, b_embed, bufA, NN, KPAD, 3);

    // ---- 3 GCN conv layers: gemm A->B, aggregate B->A ----
    for (int i = 0; i < 3; ++i) {
        sgemm_kernel<<<gridN, 256>>>(bufA, conv_w + (size_t)i * HH * HH,
                                     nullptr, bufB, NN, HH, 0);
        aggregate_kernel<<<(NN * 32 + TB - 1) / TB, TB>>>(
            bufB, conv_b + (size_t)i * HH, bufA);
    }

    // ---- global_add_pool ----
    k_gstart<<<(NN + TB - 1) / TB, TB>>>(batch);
    k_pool<<<(GG * 32) / TB, TB>>>(bufA, gA);

    // ---- FC stack ----
    dim3 gridG((GG + 127) / 128, 2);
    sgemm_kernel<<<gridG, 256>>>(gA, fc_w, fc_b, gB, GG, HH, 3);
    sgemm_kernel<<<gridG, 256>>>(gB, fc_w + HH * HH, fc_b + HH, gA, GG, HH, 3);
    sgemm_kernel<<<gridG, 256>>>(gA, fc_w + 2 * HH * HH, fc_b + 2 * HH, gB, GG, HH, 3);

    // ---- output + log_softmax ----
    k_out<<<(GG * 32) / TB, TB>>>(gB, out_w, out_b, out);
}

// round 7
// speedup vs baseline: 1.7038x; 1.7038x over previous
#include <cuda_runtime.h>
#include <cuda_bf16.h>
#include <cstdint>

// Problem constants
#define NN 50000
#define EE 800000
#define GG 2048
#define HH 256
#define KPAD 64   // 59 padded to 64

// ---------------- device scratch (no allocation allowed) ----------------
__device__ float g_bufA[NN * HH];     // 51.2 MB
__device__ float g_bufB[NN * HH];     // 51.2 MB
__device__ float g_xpad[NN * KPAD];   // 12.8 MB
__device__ float g_wpad[HH * KPAD];
__device__ int   g_deg[NN];
__device__ int   g_off[NN + 1];
__device__ int   g_cur[NN];
__device__ int   g_srcs[EE];
__device__ float g_coef[EE];
__device__ float g_dinv[NN];
__device__ int   g_gstart[GG + 1];
__device__ float g_gA[GG * HH];
__device__ float g_gB[GG * HH];

// ---------------- helpers ----------------
__device__ __forceinline__ uint32_t f2tf32(float f) {
    uint32_t r;
    asm("cvt.rna.tf32.f32 %0, %1;" : "=r"(r) : "f"(f));
    return r;
}
__device__ __forceinline__ float4 fma4(float c, float4 v, float4 a) {
    a.x += c * v.x; a.y += c * v.y; a.z += c * v.z; a.w += c * v.w;
    return a;
}
__device__ __forceinline__ float4 add4(float4 a, float4 b) {
    a.x += b.x; a.y += b.y; a.z += b.z; a.w += b.w; return a;
}

// ---------------- CSR construction ----------------
__global__ void k_zero_deg() {
    int i = blockIdx.x * blockDim.x + threadIdx.x;
    if (i < NN) g_deg[i] = 0;
}
__global__ void k_hist(const int* __restrict__ ei) {
    int e = blockIdx.x * blockDim.x + threadIdx.x;
    if (e < EE) atomicAdd(&g_deg[ei[EE + e]], 1);
}
__global__ void k_dinv() {
    int i = blockIdx.x * blockDim.x + threadIdx.x;
    if (i < NN) g_dinv[i] = rsqrtf((float)g_deg[i] + 1.0f);
}
// single-block thread-coarsened exclusive scan over g_deg -> g_off, g_cur
__global__ void __launch_bounds__(1024) k_scan() {
    __shared__ int warp_sums[32];
    __shared__ int warp_excl[32];
    const int tid = threadIdx.x;
    const int lane = tid & 31;
    const int wid = tid >> 5;
    const int ITEMS = (NN + 1023) / 1024;  // 49
    const int base = tid * ITEMS;
    int s = 0;
    for (int i = 0; i < ITEMS; ++i) {
        int idx = base + i;
        if (idx < NN) s += g_deg[idx];
    }
    int incl = s;
#pragma unroll
    for (int o = 1; o < 32; o <<= 1) {
        int t = __shfl_up_sync(0xffffffffu, incl, o);
        if (lane >= o) incl += t;
    }
    if (lane == 31) warp_sums[wid] = incl;
    __syncthreads();
    if (wid == 0) {
        int v = warp_sums[lane];
        int iv = v;
#pragma unroll
        for (int o = 1; o < 32; o <<= 1) {
            int t = __shfl_up_sync(0xffffffffu, iv, o);
            if (lane >= o) iv += t;
        }
        warp_excl[lane] = iv - v;
    }
    __syncthreads();
    int excl = warp_excl[wid] + incl - s;
    int run = excl;
    for (int i = 0; i < ITEMS; ++i) {
        int idx = base + i;
        if (idx < NN) {
            g_off[idx] = run;
            g_cur[idx] = run;
            run += g_deg[idx];
        }
    }
    if (tid == 1023) g_off[NN] = excl + s;
}
__global__ void k_scatter(const int* __restrict__ ei) {
    int e = blockIdx.x * blockDim.x + threadIdx.x;
    if (e >= EE) return;
    int s = ei[e];
    int d = ei[EE + e];
    int pos = atomicAdd(&g_cur[d], 1);
    g_srcs[pos] = s;
    g_coef[pos] = g_dinv[s];
}

// ---------------- input padding ----------------
__global__ void k_pad_x(const float* __restrict__ x) {
    int idx = blockIdx.x * blockDim.x + threadIdx.x;
    if (idx >= NN * KPAD) return;
    int i = idx / KPAD, c = idx % KPAD;
    g_xpad[idx] = (c < 59) ? x[i * 59 + c] : 0.0f;
}
__global__ void k_pad_w(const float* __restrict__ w) {
    int idx = blockIdx.x * blockDim.x + threadIdx.x;
    if (idx >= HH * KPAD) return;
    int i = idx / KPAD, c = idx % KPAD;
    g_wpad[idx] = (c < 59) ? w[i * 59 + c] : 0.0f;
}

// ---------------- tf32 mma.sync GEMM --------------------------------------
// C[M,256] = A[M,K] @ W[256,K]^T (+bias)(+relu)
// 128x128 CTA tile, 256 threads (8 warps, 2x4), warp tile 64x32,
// m16n8k8 tf32 mma, BK=32 smem chunks, pad-36 rows (bank-conflict free).
#define BK 32
#define PADR 36

__global__ void __launch_bounds__(256) gemm_tf32_kernel(
    const float* __restrict__ A, const float* __restrict__ W,
    const float* __restrict__ bias, float* __restrict__ C,
    int M, int K, int flags) {
    __shared__ __align__(16) uint32_t sA[128 * PADR];
    __shared__ __align__(16) uint32_t sB[128 * PADR];
    __shared__ float sBias[128];

    const int tid = threadIdx.x;
    const int wid = tid >> 5;
    const int lane = tid & 31;
    const int m0 = blockIdx.x * 128;
    const int n0 = blockIdx.y * 128;
    const int warp_m = (wid >> 2) * 64;   // 0 or 64
    const int warp_n = (wid & 3) * 32;    // 0/32/64/96

    if (tid < 128) sBias[tid] = (flags & 1) ? bias[n0 + tid] : 0.0f;

    float acc[4][4][4];
#pragma unroll
    for (int mt = 0; mt < 4; ++mt)
#pragma unroll
        for (int nt = 0; nt < 4; ++nt)
#pragma unroll
            for (int r = 0; r < 4; ++r) acc[mt][nt][r] = 0.0f;

    // fill mapping: thread handles row tr = tid>>1, 16 floats at col (tid&1)*16
    const int tr = tid >> 1;
    const int tc = (tid & 1) * 16;
    const bool a_valid = (m0 + tr) < M;
    const float* arow = A + (size_t)(m0 + tr) * K + tc;
    const float* wrow = W + (size_t)(n0 + tr) * K + tc;
    uint32_t* sAp = &sA[tr * PADR + tc];
    uint32_t* sBp = &sB[tr * PADR + tc];

    const int lg = lane >> 2;   // 0..7
    const int lt = lane & 3;    // 0..3

    for (int k0 = 0; k0 < K; k0 += BK) {
#pragma unroll
        for (int j = 0; j < 4; ++j) {
            float4 v = a_valid ? *(const float4*)(arow + k0 + j * 4)
                               : make_float4(0.f, 0.f, 0.f, 0.f);
            uint4 t;
            t.x = f2tf32(v.x); t.y = f2tf32(v.y);
            t.z = f2tf32(v.z); t.w = f2tf32(v.w);
            *(uint4*)(sAp + j * 4) = t;
        }
#pragma unroll
        for (int j = 0; j < 4; ++j) {
            float4 v = *(const float4*)(wrow + k0 + j * 4);
            uint4 t;
            t.x = f2tf32(v.x); t.y = f2tf32(v.y);
            t.z = f2tf32(v.z); t.w = f2tf32(v.w);
            *(uint4*)(sBp + j * 4) = t;
        }
        __syncthreads();

#pragma unroll
        for (int kk = 0; kk < BK; kk += 8) {
            uint32_t afr[4][4];
            uint32_t bfr[4][2];
#pragma unroll
            for (int mt = 0; mt < 4; ++mt) {
                int ar = warp_m + mt * 16 + lg;
                afr[mt][0] = sA[ar * PADR + kk + lt];
                afr[mt][1] = sA[(ar + 8) * PADR + kk + lt];
                afr[mt][2] = sA[ar * PADR + kk + lt + 4];
                afr[mt][3] = sA[(ar + 8) * PADR + kk + lt + 4];
            }
#pragma unroll
            for (int nt = 0; nt < 4; ++nt) {
                int bn = warp_n + nt * 8 + lg;
                bfr[nt][0] = sB[bn * PADR + kk + lt];
                bfr[nt][1] = sB[bn * PADR + kk + lt + 4];
            }
#pragma unroll
            for (int mt = 0; mt < 4; ++mt) {
#pragma unroll
                for (int nt = 0; nt < 4; ++nt) {
                    asm volatile(
                        "mma.sync.aligned.m16n8k8.row.col.f32.tf32.tf32.f32 "
                        "{%0,%1,%2,%3}, {%4,%5,%6,%7}, {%8,%9}, {%0,%1,%2,%3};\n"
                        : "+f"(acc[mt][nt][0]), "+f"(acc[mt][nt][1]),
                          "+f"(acc[mt][nt][2]), "+f"(acc[mt][nt][3])
                        : "r"(afr[mt][0]), "r"(afr[mt][1]),
                          "r"(afr[mt][2]), "r"(afr[mt][3]),
                          "r"(bfr[nt][0]), "r"(bfr[nt][1]));
                }
            }
        }
        __syncthreads();
    }

    // epilogue
    const bool do_relu = (flags & 2) != 0;
#pragma unroll
    for (int mt = 0; mt < 4; ++mt) {
        int r0 = m0 + warp_m + mt * 16 + lg;
        int r1 = r0 + 8;
#pragma unroll
        for (int nt = 0; nt < 4; ++nt) {
            int cl = warp_n + nt * 8 + lt * 2;     // local col in [0,128)
            float b0 = sBias[cl], b1 = sBias[cl + 1];
            int col = n0 + cl;
            float v0 = acc[mt][nt][0] + b0;
            float v1 = acc[mt][nt][1] + b1;
            float v2 = acc[mt][nt][2] + b0;
            float v3 = acc[mt][nt][3] + b1;
            if (do_relu) {
                v0 = fmaxf(v0, 0.f); v1 = fmaxf(v1, 0.f);
                v2 = fmaxf(v2, 0.f); v3 = fmaxf(v3, 0.f);
            }
            if (r0 < M) *(float2*)(C + (size_t)r0 * 256 + col) = make_float2(v0, v1);
            if (r1 < M) *(float2*)(C + (size_t)r1 * 256 + col) = make_float2(v2, v3);
        }
    }
}

// ---------------- GCN aggregation: warp per node, gather-only ----------
__global__ void aggregate_kernel(const float* __restrict__ h2,
                                 const float* __restrict__ bias,
                                 float* __restrict__ out) {
    int warp = (blockIdx.x * blockDim.x + threadIdx.x) >> 5;
    if (warp >= NN) return;
    int lane = threadIdx.x & 31;
    float4 acc0 = make_float4(0.f, 0.f, 0.f, 0.f);
    float4 acc1 = make_float4(0.f, 0.f, 0.f, 0.f);
    int s = g_off[warp], e = g_off[warp + 1];
    int j = s;
    for (; j + 1 < e; j += 2) {
        int s0 = g_srcs[j], s1 = g_srcs[j + 1];
        float c0 = g_coef[j], c1 = g_coef[j + 1];
        const float4* r0 = (const float4*)(h2 + (size_t)s0 * 256);
        const float4* r1 = (const float4*)(h2 + (size_t)s1 * 256);
        float4 v00 = r0[lane], v01 = r0[lane + 32];
        float4 v10 = r1[lane], v11 = r1[lane + 32];
        acc0 = fma4(c0, v00, acc0);
        acc1 = fma4(c0, v01, acc1);
        acc0 = fma4(c1, v10, acc0);
        acc1 = fma4(c1, v11, acc1);
    }
    if (j < e) {
        int s0 = g_srcs[j];
        float c0 = g_coef[j];
        const float4* r0 = (const float4*)(h2 + (size_t)s0 * 256);
        acc0 = fma4(c0, r0[lane], acc0);
        acc1 = fma4(c0, r0[lane + 32], acc1);
    }
    float di = g_dinv[warp];
    float d2 = di * di;
    const float4* self = (const float4*)(h2 + (size_t)warp * 256);
    float4 s0v = self[lane], s1v = self[lane + 32];
    const float4* b = (const float4*)bias;
    float4 b0 = b[lane], b1 = b[lane + 32];
    float4 o0, o1;
    o0.x = fmaxf(acc0.x * di + d2 * s0v.x + b0.x, 0.0f);
    o0.y = fmaxf(acc0.y * di + d2 * s0v.y + b0.y, 0.0f);
    o0.z = fmaxf(acc0.z * di + d2 * s0v.z + b0.z, 0.0f);
    o0.w = fmaxf(acc0.w * di + d2 * s0v.w + b0.w, 0.0f);
    o1.x = fmaxf(acc1.x * di + d2 * s1v.x + b1.x, 0.0f);
    o1.y = fmaxf(acc1.y * di + d2 * s1v.y + b1.y, 0.0f);
    o1.z = fmaxf(acc1.z * di + d2 * s1v.z + b1.z, 0.0f);
    o1.w = fmaxf(acc1.w * di + d2 * s1v.w + b1.w, 0.0f);
    float4* orow = (float4*)(out + (size_t)warp * 256);
    orow[lane] = o0;
    orow[lane + 32] = o1;
}

// ---------------- pooling ----------------
__global__ void k_gstart(const int* __restrict__ batch) {
    int i = blockIdx.x * blockDim.x + threadIdx.x;
    if (i >= NN) return;
    int b = batch[i];
    int prev = (i == 0) ? -1 : batch[i - 1];
    for (int g = prev + 1; g <= b; ++g) g_gstart[g] = i;
    if (i == NN - 1) {
        for (int g = b + 1; g <= GG; ++g) g_gstart[g] = NN;
    }
}
__global__ void k_pool(const float* __restrict__ h, float* __restrict__ out) {
    int warp = (blockIdx.x * blockDim.x + threadIdx.x) >> 5;
    if (warp >= GG) return;
    int lane = threadIdx.x & 31;
    float4 acc0 = make_float4(0.f, 0.f, 0.f, 0.f);
    float4 acc1 = make_float4(0.f, 0.f, 0.f, 0.f);
    int s = g_gstart[warp], e = g_gstart[warp + 1];
    for (int i = s; i < e; ++i) {
        const float4* r = (const float4*)(h + (size_t)i * 256);
        acc0 = add4(acc0, r[lane]);
        acc1 = add4(acc1, r[lane + 32]);
    }
    float4* orow = (float4*)(out + (size_t)warp * 256);
    orow[lane] = acc0;
    orow[lane + 32] = acc1;
}

// ---------------- output head: 2 dots + log_softmax, warp per graph -----
__global__ void k_out(const float* __restrict__ g,
                      const float* __restrict__ out_w,
                      const float* __restrict__ out_b,
                      float* __restrict__ out) {
    int warp = (blockIdx.x * blockDim.x + threadIdx.x) >> 5;
    if (warp >= GG) return;
    int lane = threadIdx.x & 31;
    const float* row = g + (size_t)warp * 256;
    float p0 = 0.f, p1 = 0.f;
    for (int k = lane; k < 256; k += 32) {
        float v = row[k];
        p0 += v * out_w[k];
        p1 += v * out_w[256 + k];
    }
#pragma unroll
    for (int o = 16; o; o >>= 1) {
        p0 += __shfl_down_sync(0xffffffffu, p0, o);
        p1 += __shfl_down_sync(0xffffffffu, p1, o);
    }
    if (lane == 0) {
        float z0 = p0 + out_b[0];
        float z1 = p1 + out_b[1];
        float m = fmaxf(z0, z1);
        float lse = m + logf(expf(z0 - m) + expf(z1 - m));
        out[warp * 2 + 0] = z0 - lse;
        out[warp * 2 + 1] = z1 - lse;
    }
}

// ---------------- launch ----------------
extern "C" void kernel_launch(void* const* d_in, const int* in_sizes, int n_in,
                              void* d_out, int out_size) {
    const float* x       = (const float*)d_in[0];
    const int*   ei      = (const int*)d_in[1];
    const int*   batch   = (const int*)d_in[2];
    const float* W_embed = (const float*)d_in[3];
    const float* b_embed = (const float*)d_in[4];
    const float* conv_w  = (const float*)d_in[5];
    const float* conv_b  = (const float*)d_in[6];
    const float* fc_w    = (const float*)d_in[7];
    const float* fc_b    = (const float*)d_in[8];
    const float* out_w   = (const float*)d_in[9];
    const float* out_b   = (const float*)d_in[10];
    float* out = (float*)d_out;

    float *bufA, *bufB, *xpad, *wpad, *gA, *gB;
    cudaGetSymbolAddress((void**)&bufA, g_bufA);
    cudaGetSymbolAddress((void**)&bufB, g_bufB);
    cudaGetSymbolAddress((void**)&xpad, g_xpad);
    cudaGetSymbolAddress((void**)&wpad, g_wpad);
    cudaGetSymbolAddress((void**)&gA, g_gA);
    cudaGetSymbolAddress((void**)&gB, g_gB);

    const int TB = 256;
    // ---- CSR build ----
    k_zero_deg<<<(NN + TB - 1) / TB, TB>>>();
    k_hist<<<(EE + TB - 1) / TB, TB>>>(ei);
    k_dinv<<<(NN + TB - 1) / TB, TB>>>();
    k_scan<<<1, 1024>>>();
    k_scatter<<<(EE + TB - 1) / TB, TB>>>(ei);

    // ---- embed: relu(x @ W_embed^T + b), K padded to 64 ----
    k_pad_x<<<(NN * KPAD + TB - 1) / TB, TB>>>(x);
    k_pad_w<<<(HH * KPAD + TB - 1) / TB, TB>>>(W_embed);
    dim3 gridN((NN + 127) / 128, 2);
    gemm_tf32_kernel<<<gridN, 256>>>(xpad, wpad, b_embed, bufA, NN, KPAD, 3);

    // ---- 3 GCN conv layers: gemm A->B, aggregate B->A ----
    for (int i = 0; i < 3; ++i) {
        gemm_tf32_kernel<<<gridN, 256>>>(bufA, conv_w + (size_t)i * HH * HH,
                                         nullptr, bufB, NN, HH, 0);
        aggregate_kernel<<<(NN * 32 + TB - 1) / TB, TB>>>(
            bufB, conv_b + (size_t)i * HH, bufA);
    }

    // ---- global_add_pool ----
    k_gstart<<<(NN + TB - 1) / TB, TB>>>(batch);
    k_pool<<<(GG * 32) / TB, TB>>>(bufA, gA);

    // ---- FC stack ----
    dim3 gridG((GG + 127) / 128, 2);
    gemm_tf32_kernel<<<gridG, 256>>>(gA, fc_w, fc_b, gB, GG, HH, 3);
    gemm_tf32_kernel<<<gridG, 256>>>(gB, fc_w + HH * HH, fc_b + HH, gA, GG, HH, 3);
    gemm_tf32_kernel<<<gridG, 256>>>(gA, fc_w + 2 * HH * HH, fc_b + 2 * HH, gB, GG, HH, 3);

    // ---- output + log_softmax ----
    k_out<<<(GG * 32) / TB, TB>>>(gB, out_w, out_b, out);
}

// round 8
// speedup vs baseline: 1.9144x; 1.1236x over previous
#include <cuda_runtime.h>
#include <cstdint>

// Problem constants
#define NN 50000
#define EE 800000
#define GG 2048
#define HH 256
#define KPAD 64   // 59 padded to 64

// ---------------- device scratch (no allocation allowed) ----------------
__device__ float g_bufA[NN * HH];     // 51.2 MB
__device__ float g_bufB[NN * HH];     // 51.2 MB
__device__ float g_xpad[NN * KPAD];   // 12.8 MB
__device__ float g_wpad[HH * KPAD];
__device__ float g_wconv[3 * HH * HH];
__device__ float g_wfc[3 * HH * HH];
__device__ int   g_deg[NN];
__device__ int   g_off[NN + 1];
__device__ int   g_cur[NN];
__device__ int   g_srcs[EE];
__device__ float g_coef[EE];
__device__ float g_dinv[NN];
__device__ int   g_gstart[GG + 1];
__device__ float g_gA[GG * HH];
__device__ float g_gB[GG * HH];

// ---------------- helpers ----------------
__device__ __forceinline__ uint32_t f2tf32(float f) {
    uint32_t r;
    asm("cvt.rna.tf32.f32 %0, %1;" : "=r"(r) : "f"(f));
    return r;
}
__device__ __forceinline__ float roundtf(float f) {
    return __uint_as_float(f2tf32(f));
}
__device__ __forceinline__ float4 fma4(float c, float4 v, float4 a) {
    a.x += c * v.x; a.y += c * v.y; a.z += c * v.z; a.w += c * v.w;
    return a;
}
__device__ __forceinline__ float4 add4(float4 a, float4 b) {
    a.x += b.x; a.y += b.y; a.z += b.z; a.w += b.w; return a;
}
__device__ __forceinline__ void cp16(uint32_t dst, const void* src, uint32_t sz) {
    asm volatile("cp.async.cg.shared.global [%0], [%1], 16, %2;\n"
                 :: "r"(dst), "l"(src), "r"(sz));
}

// ---------------- CSR construction ----------------
__global__ void k_zero_deg() {
    int i = blockIdx.x * blockDim.x + threadIdx.x;
    if (i < NN) g_deg[i] = 0;
}
__global__ void k_hist(const int* __restrict__ ei) {
    int e = blockIdx.x * blockDim.x + threadIdx.x;
    if (e < EE) atomicAdd(&g_deg[ei[EE + e]], 1);
}
__global__ void k_dinv() {
    int i = blockIdx.x * blockDim.x + threadIdx.x;
    if (i < NN) g_dinv[i] = rsqrtf((float)g_deg[i] + 1.0f);
}
// single-block scan with smem staging: coalesced in, coalesced out
__global__ void __launch_bounds__(1024) k_scan() {
    extern __shared__ int sd[];            // NN ints (200 KB)
    __shared__ int warp_sums[32];
    __shared__ int warp_excl[32];
    const int tid = threadIdx.x;
    const int lane = tid & 31;
    const int wid = tid >> 5;
    const int ITEMS = (NN + 1023) / 1024;  // 49
    // coalesced stage-in
    for (int i = tid; i < NN; i += 1024) sd[i] = g_deg[i];
    __syncthreads();
    const int base = tid * ITEMS;
    int s = 0;
    for (int i = 0; i < ITEMS; ++i) {
        int idx = base + i;
        if (idx < NN) s += sd[idx];
    }
    int incl = s;
#pragma unroll
    for (int o = 1; o < 32; o <<= 1) {
        int t = __shfl_up_sync(0xffffffffu, incl, o);
        if (lane >= o) incl += t;
    }
    if (lane == 31) warp_sums[wid] = incl;
    __syncthreads();
    if (wid == 0) {
        int v = warp_sums[lane];
        int iv = v;
#pragma unroll
        for (int o = 1; o < 32; o <<= 1) {
            int t = __shfl_up_sync(0xffffffffu, iv, o);
            if (lane >= o) iv += t;
        }
        warp_excl[lane] = iv - v;
    }
    __syncthreads();
    int excl = warp_excl[wid] + incl - s;
    int run = excl;
    for (int i = 0; i < ITEMS; ++i) {
        int idx = base + i;
        if (idx < NN) {
            int v = sd[idx];
            sd[idx] = run;          // in-place: deg -> exclusive prefix
            run += v;
        }
    }
    __syncthreads();
    // coalesced stage-out
    for (int i = tid; i < NN; i += 1024) {
        int v = sd[i];
        g_off[i] = v;
        g_cur[i] = v;
    }
    if (tid == 1023) g_off[NN] = excl + s;
}
__global__ void k_scatter(const int* __restrict__ ei) {
    int e = blockIdx.x * blockDim.x + threadIdx.x;
    if (e >= EE) return;
    int s = ei[e];
    int d = ei[EE + e];
    int pos = atomicAdd(&g_cur[d], 1);
    g_srcs[pos] = s;
    g_coef[pos] = g_dinv[s];
}

// ---------------- input padding / weight rounding (all tf32-rounded) ----
__global__ void k_pad_x(const float* __restrict__ x) {
    int idx = blockIdx.x * blockDim.x + threadIdx.x;
    if (idx >= NN * KPAD) return;
    int i = idx / KPAD, c = idx % KPAD;
    g_xpad[idx] = (c < 59) ? roundtf(x[i * 59 + c]) : 0.0f;
}
__global__ void k_pad_w(const float* __restrict__ w) {
    int idx = blockIdx.x * blockDim.x + threadIdx.x;
    if (idx >= HH * KPAD) return;
    int i = idx / KPAD, c = idx % KPAD;
    g_wpad[idx] = (c < 59) ? roundtf(w[i * 59 + c]) : 0.0f;
}
__global__ void k_round(const float* __restrict__ src, float* __restrict__ dst,
                        int n) {
    int i = blockIdx.x * blockDim.x + threadIdx.x;
    if (i < n) dst[i] = roundtf(src[i]);
}

// ---------------- tf32 mma.sync GEMM, cp.async double-buffered -----------
// C[M,256] = A[M,K] @ W[256,K]^T (+bias)(+relu)(+round-out)
// A and W must be pre-rounded to tf32 bit patterns.
// 128x128 CTA tile, 256 threads (8 warps 2x4), warp tile 64x32, m16n8k8.
#define BK 32
#define PADR 36
#define CH (128 * PADR)   // words per operand tile

__global__ void __launch_bounds__(256, 2) gemm_tf32_kernel(
    const float* __restrict__ A, const float* __restrict__ W,
    const float* __restrict__ bias, float* __restrict__ C,
    int M, int K, int flags) {
    extern __shared__ uint32_t sm[];   // [A0 | B0 | A1 | B1], CH words each
    __shared__ float sBias[128];

    const int tid = threadIdx.x;
    const int wid = tid >> 5;
    const int lane = tid & 31;
    const int m0 = blockIdx.x * 128;
    const int n0 = blockIdx.y * 128;
    const int warp_m = (wid >> 2) * 64;
    const int warp_n = (wid & 3) * 32;

    if (tid < 128) sBias[tid] = (flags & 1) ? bias[n0 + tid] : 0.0f;

    float acc[4][4][4];
#pragma unroll
    for (int mt = 0; mt < 4; ++mt)
#pragma unroll
        for (int nt = 0; nt < 4; ++nt)
#pragma unroll
            for (int r = 0; r < 4; ++r) acc[mt][nt][r] = 0.0f;

    // fill mapping: thread -> row tr, 16 cols at tc
    const int tr = tid >> 1;
    const int tc = (tid & 1) * 16;
    const bool a_valid = (m0 + tr) < M;
    const uint32_t a_sz = a_valid ? 16u : 0u;
    const float* arow = A + (size_t)(a_valid ? (m0 + tr) : 0) * K + tc;
    const float* wrow = W + (size_t)(n0 + tr) * K + tc;
    const uint32_t sbase = (uint32_t)__cvta_generic_to_shared(sm);
    const uint32_t sAoff = sbase + (uint32_t)(tr * PADR + tc) * 4u;

    const int lg = lane >> 2;
    const int lt = lane & 3;
    const int nch = K / BK;

    // prologue: issue chunk 0 into buffer 0
#pragma unroll
    for (int j = 0; j < 4; ++j)
        cp16(sAoff + j * 16u, arow + j * 4, a_sz);
#pragma unroll
    for (int j = 0; j < 4; ++j)
        cp16(sAoff + CH * 4u + j * 16u, wrow + j * 4, 16u);
    asm volatile("cp.async.commit_group;\n");

    for (int c = 0; c < nch; ++c) {
        if (c + 1 < nch) {
            uint32_t boff = sAoff + ((c + 1) & 1) * (2u * CH * 4u);
            const float* ap = arow + (c + 1) * BK;
            const float* wp = wrow + (c + 1) * BK;
#pragma unroll
            for (int j = 0; j < 4; ++j)
                cp16(boff + j * 16u, ap + j * 4, a_sz);
#pragma unroll
            for (int j = 0; j < 4; ++j)
                cp16(boff + CH * 4u + j * 16u, wp + j * 4, 16u);
            asm volatile("cp.async.commit_group;\n");
            asm volatile("cp.async.wait_group 1;\n");
        } else {
            asm volatile("cp.async.wait_group 0;\n");
        }
        __syncthreads();

        const uint32_t* sA = sm + (c & 1) * (2 * CH);
        const uint32_t* sB = sA + CH;
#pragma unroll
        for (int kk = 0; kk < BK; kk += 8) {
            uint32_t afr[4][4];
            uint32_t bfr[4][2];
#pragma unroll
            for (int mt = 0; mt < 4; ++mt) {
                int ar = warp_m + mt * 16 + lg;
                afr[mt][0] = sA[ar * PADR + kk + lt];
                afr[mt][1] = sA[(ar + 8) * PADR + kk + lt];
                afr[mt][2] = sA[ar * PADR + kk + lt + 4];
                afr[mt][3] = sA[(ar + 8) * PADR + kk + lt + 4];
            }
#pragma unroll
            for (int nt = 0; nt < 4; ++nt) {
                int bn = warp_n + nt * 8 + lg;
                bfr[nt][0] = sB[bn * PADR + kk + lt];
                bfr[nt][1] = sB[bn * PADR + kk + lt + 4];
            }
#pragma unroll
            for (int mt = 0; mt < 4; ++mt) {
#pragma unroll
                for (int nt = 0; nt < 4; ++nt) {
                    asm volatile(
                        "mma.sync.aligned.m16n8k8.row.col.f32.tf32.tf32.f32 "
                        "{%0,%1,%2,%3}, {%4,%5,%6,%7}, {%8,%9}, {%0,%1,%2,%3};\n"
                        : "+f"(acc[mt][nt][0]), "+f"(acc[mt][nt][1]),
                          "+f"(acc[mt][nt][2]), "+f"(acc[mt][nt][3])
                        : "r"(afr[mt][0]), "r"(afr[mt][1]),
                          "r"(afr[mt][2]), "r"(afr[mt][3]),
                          "r"(bfr[nt][0]), "r"(bfr[nt][1]));
                }
            }
        }
        __syncthreads();
    }

    // epilogue
    const bool do_relu = (flags & 2) != 0;
    const bool do_round = (flags & 4) != 0;
#pragma unroll
    for (int mt = 0; mt < 4; ++mt) {
        int r0 = m0 + warp_m + mt * 16 + lg;
        int r1 = r0 + 8;
#pragma unroll
        for (int nt = 0; nt < 4; ++nt) {
            int cl = warp_n + nt * 8 + lt * 2;
            float b0 = sBias[cl], b1 = sBias[cl + 1];
            int col = n0 + cl;
            float v0 = acc[mt][nt][0] + b0;
            float v1 = acc[mt][nt][1] + b1;
            float v2 = acc[mt][nt][2] + b0;
            float v3 = acc[mt][nt][3] + b1;
            if (do_relu) {
                v0 = fmaxf(v0, 0.f); v1 = fmaxf(v1, 0.f);
                v2 = fmaxf(v2, 0.f); v3 = fmaxf(v3, 0.f);
            }
            if (do_round) {
                v0 = roundtf(v0); v1 = roundtf(v1);
                v2 = roundtf(v2); v3 = roundtf(v3);
            }
            if (r0 < M) *(float2*)(C + (size_t)r0 * 256 + col) = make_float2(v0, v1);
            if (r1 < M) *(float2*)(C + (size_t)r1 * 256 + col) = make_float2(v2, v3);
        }
    }
}

// ---------------- GCN aggregation: warp per node, gather-only ----------
// Output is tf32-rounded (it feeds the next GEMM's A operand).
__global__ void aggregate_kernel(const float* __restrict__ h2,
                                 const float* __restrict__ bias,
                                 float* __restrict__ out) {
    int warp = (blockIdx.x * blockDim.x + threadIdx.x) >> 5;
    if (warp >= NN) return;
    int lane = threadIdx.x & 31;
    float4 acc0 = make_float4(0.f, 0.f, 0.f, 0.f);
    float4 acc1 = make_float4(0.f, 0.f, 0.f, 0.f);
    int s = g_off[warp], e = g_off[warp + 1];
    int j = s;
    for (; j + 1 < e; j += 2) {
        int s0 = g_srcs[j], s1 = g_srcs[j + 1];
        float c0 = g_coef[j], c1 = g_coef[j + 1];
        const float4* r0 = (const float4*)(h2 + (size_t)s0 * 256);
        const float4* r1 = (const float4*)(h2 + (size_t)s1 * 256);
        float4 v00 = r0[lane], v01 = r0[lane + 32];
        float4 v10 = r1[lane], v11 = r1[lane + 32];
        acc0 = fma4(c0, v00, acc0);
        acc1 = fma4(c0, v01, acc1);
        acc0 = fma4(c1, v10, acc0);
        acc1 = fma4(c1, v11, acc1);
    }
    if (j < e) {
        int s0 = g_srcs[j];
        float c0 = g_coef[j];
        const float4* r0 = (const float4*)(h2 + (size_t)s0 * 256);
        acc0 = fma4(c0, r0[lane], acc0);
        acc1 = fma4(c0, r0[lane + 32], acc1);
    }
    float di = g_dinv[warp];
    float d2 = di * di;
    const float4* self = (const float4*)(h2 + (size_t)warp * 256);
    float4 s0v = self[lane], s1v = self[lane + 32];
    const float4* b = (const float4*)bias;
    float4 b0 = b[lane], b1 = b[lane + 32];
    float4 o0, o1;
    o0.x = roundtf(fmaxf(acc0.x * di + d2 * s0v.x + b0.x, 0.0f));
    o0.y = roundtf(fmaxf(acc0.y * di + d2 * s0v.y + b0.y, 0.0f));
    o0.z = roundtf(fmaxf(acc0.z * di + d2 * s0v.z + b0.z, 0.0f));
    o0.w = roundtf(fmaxf(acc0.w * di + d2 * s0v.w + b0.w, 0.0f));
    o1.x = roundtf(fmaxf(acc1.x * di + d2 * s1v.x + b1.x, 0.0f));
    o1.y = roundtf(fmaxf(acc1.y * di + d2 * s1v.y + b1.y, 0.0f));
    o1.z = roundtf(fmaxf(acc1.z * di + d2 * s1v.z + b1.z, 0.0f));
    o1.w = roundtf(fmaxf(acc1.w * di + d2 * s1v.w + b1.w, 0.0f));
    float4* orow = (float4*)(out + (size_t)warp * 256);
    orow[lane] = o0;
    orow[lane + 32] = o1;
}

// ---------------- pooling ----------------
__global__ void k_gstart(const int* __restrict__ batch) {
    int i = blockIdx.x * blockDim.x + threadIdx.x;
    if (i >= NN) return;
    int b = batch[i];
    int prev = (i == 0) ? -1 : batch[i - 1];
    for (int g = prev + 1; g <= b; ++g) g_gstart[g] = i;
    if (i == NN - 1) {
        for (int g = b + 1; g <= GG; ++g) g_gstart[g] = NN;
    }
}
__global__ void k_pool(const float* __restrict__ h, float* __restrict__ out) {
    int warp = (blockIdx.x * blockDim.x + threadIdx.x) >> 5;
    if (warp >= GG) return;
    int lane = threadIdx.x & 31;
    float4 acc0 = make_float4(0.f, 0.f, 0.f, 0.f);
    float4 acc1 = make_float4(0.f, 0.f, 0.f, 0.f);
    int s = g_gstart[warp], e = g_gstart[warp + 1];
    for (int i = s; i < e; ++i) {
        const float4* r = (const float4*)(h + (size_t)i * 256);
        acc0 = add4(acc0, r[lane]);
        acc1 = add4(acc1, r[lane + 32]);
    }
    acc0.x = roundtf(acc0.x); acc0.y = roundtf(acc0.y);
    acc0.z = roundtf(acc0.z); acc0.w = roundtf(acc0.w);
    acc1.x = roundtf(acc1.x); acc1.y = roundtf(acc1.y);
    acc1.z = roundtf(acc1.z); acc1.w = roundtf(acc1.w);
    float4* orow = (float4*)(out + (size_t)warp * 256);
    orow[lane] = acc0;
    orow[lane + 32] = acc1;
}

// ---------------- output head: 2 dots + log_softmax, warp per graph -----
__global__ void k_out(const float* __restrict__ g,
                      const float* __restrict__ out_w,
                      const float* __restrict__ out_b,
                      float* __restrict__ out) {
    int warp = (blockIdx.x * blockDim.x + threadIdx.x) >> 5;
    if (warp >= GG) return;
    int lane = threadIdx.x & 31;
    const float* row = g + (size_t)warp * 256;
    float p0 = 0.f, p1 = 0.f;
    for (int k = lane; k < 256; k += 32) {
        float v = row[k];
        p0 += v * out_w[k];
        p1 += v * out_w[256 + k];
    }
#pragma unroll
    for (int o = 16; o; o >>= 1) {
        p0 += __shfl_down_sync(0xffffffffu, p0, o);
        p1 += __shfl_down_sync(0xffffffffu, p1, o);
    }
    if (lane == 0) {
        float z0 = p0 + out_b[0];
        float z1 = p1 + out_b[1];
        float m = fmaxf(z0, z1);
        float lse = m + logf(expf(z0 - m) + expf(z1 - m));
        out[warp * 2 + 0] = z0 - lse;
        out[warp * 2 + 1] = z1 - lse;
    }
}

// ---------------- launch ----------------
extern "C" void kernel_launch(void* const* d_in, const int* in_sizes, int n_in,
                              void* d_out, int out_size) {
    const float* x       = (const float*)d_in[0];
    const int*   ei      = (const int*)d_in[1];
    const int*   batch   = (const int*)d_in[2];
    const float* W_embed = (const float*)d_in[3];
    const float* b_embed = (const float*)d_in[4];
    const float* conv_w  = (const float*)d_in[5];
    const float* conv_b  = (const float*)d_in[6];
    const float* fc_w    = (const float*)d_in[7];
    const float* fc_b    = (const float*)d_in[8];
    const float* out_w   = (const float*)d_in[9];
    const float* out_b   = (const float*)d_in[10];
    float* out = (float*)d_out;

    float *bufA, *bufB, *xpad, *wpad, *wconv, *wfc, *gA, *gB;
    cudaGetSymbolAddress((void**)&bufA, g_bufA);
    cudaGetSymbolAddress((void**)&bufB, g_bufB);
    cudaGetSymbolAddress((void**)&xpad, g_xpad);
    cudaGetSymbolAddress((void**)&wpad, g_wpad);
    cudaGetSymbolAddress((void**)&wconv, g_wconv);
    cudaGetSymbolAddress((void**)&wfc, g_wfc);
    cudaGetSymbolAddress((void**)&gA, g_gA);
    cudaGetSymbolAddress((void**)&gB, g_gB);

    static bool attr_done = false;
    if (!attr_done) {
        cudaFuncSetAttribute(k_scan, cudaFuncAttributeMaxDynamicSharedMemorySize,
                             NN * (int)sizeof(int));
        cudaFuncSetAttribute(gemm_tf32_kernel,
                             cudaFuncAttributeMaxDynamicSharedMemorySize,
                             4 * CH * (int)sizeof(uint32_t));
        attr_done = true;
    }
    const int GEMM_SMEM = 4 * CH * (int)sizeof(uint32_t);  // 73728

    const int TB = 256;
    // ---- CSR build ----
    k_zero_deg<<<(NN + TB - 1) / TB, TB>>>();
    k_hist<<<(EE + TB - 1) / TB, TB>>>(ei);
    k_dinv<<<(NN + TB - 1) / TB, TB>>>();
    k_scan<<<1, 1024, NN * sizeof(int)>>>();
    k_scatter<<<(EE + TB - 1) / TB, TB>>>(ei);

    // ---- pad/round inputs & weights (tf32) ----
    k_pad_x<<<(NN * KPAD + TB - 1) / TB, TB>>>(x);
    k_pad_w<<<(HH * KPAD + TB - 1) / TB, TB>>>(W_embed);
    k_round<<<(3 * HH * HH + TB - 1) / TB, TB>>>(conv_w, wconv, 3 * HH * HH);
    k_round<<<(3 * HH * HH + TB - 1) / TB, TB>>>(fc_w, wfc, 3 * HH * HH);

    // ---- embed: relu(x @ W_embed^T + b), round output ----
    dim3 gridN((NN + 127) / 128, 2);
    gemm_tf32_kernel<<<gridN, 256, GEMM_SMEM>>>(xpad, wpad, b_embed, bufA,
                                                NN, KPAD, 7);

    // ---- 3 GCN conv layers: gemm A->B, aggregate B->A ----
    for (int i = 0; i < 3; ++i) {
        gemm_tf32_kernel<<<gridN, 256, GEMM_SMEM>>>(
            bufA, wconv + (size_t)i * HH * HH, nullptr, bufB, NN, HH, 0);
        aggregate_kernel<<<(NN * 32 + TB - 1) / TB, TB>>>(
            bufB, conv_b + (size_t)i * HH, bufA);
    }

    // ---- global_add_pool (rounded) ----
    k_gstart<<<(NN + TB - 1) / TB, TB>>>(batch);
    k_pool<<<(GG * 32) / TB, TB>>>(bufA, gA);

    // ---- FC stack (rounded outputs) ----
    dim3 gridG((GG + 127) / 128, 2);
    gemm_tf32_kernel<<<gridG, 256, GEMM_SMEM>>>(gA, wfc, fc_b, gB, GG, HH, 7);
    gemm_tf32_kernel<<<gridG, 256, GEMM_SMEM>>>(gB, wfc + HH * HH, fc_b + HH,
                                                gA, GG, HH, 7);
    gemm_tf32_kernel<<<gridG, 256, GEMM_SMEM>>>(gA, wfc + 2 * HH * HH,
                                                fc_b + 2 * HH, gB, GG, HH, 7);

    // ---- output + log_softmax ----
    k_out<<<(GG * 32) / TB, TB>>>(gB, out_w, out_b, out);
}

// round 9
// speedup vs baseline: 2.9729x; 1.5529x over previous
#include <cuda_runtime.h>
#include <cuda_fp16.h>
#include <cstdint>

// Problem constants
#define NN 50000
#define EE 800000
#define GG 2048
#define HH 256
#define KPAD 64   // 59 padded to 64

// ---------------- device scratch (no allocation allowed) ----------------
__device__ __half g_bufA[NN * HH];     // 25.6 MB (activations, fp16)
__device__ __half g_bufB[NN * HH];     // 25.6 MB
__device__ __half g_xpad[NN * KPAD];   // 6.4 MB
__device__ __half g_wpad[HH * KPAD];
__device__ __half g_wconv[3 * HH * HH];
__device__ __half g_wfc[3 * HH * HH];
__device__ int    g_deg[NN];
__device__ int    g_off[NN + 1];
__device__ int    g_cur[NN];
__device__ int    g_srcs[EE];
__device__ float  g_coef[EE];
__device__ float  g_dinv[NN];
__device__ int    g_gstart[GG + 1];
__device__ __half g_gA[GG * HH];
__device__ __half g_gB[GG * HH];

// ---------------- helpers ----------------
__device__ __forceinline__ void cp16(uint32_t dst, const void* src, uint32_t sz) {
    asm volatile("cp.async.cg.shared.global [%0], [%1], 16, %2;\n"
                 :: "r"(dst), "l"(src), "r"(sz));
}

// ---------------- CSR construction ----------------
__global__ void k_zero_deg() {
    int i = blockIdx.x * blockDim.x + threadIdx.x;
    if (i < NN) g_deg[i] = 0;
}
__global__ void k_hist(const int* __restrict__ ei) {
    int e = blockIdx.x * blockDim.x + threadIdx.x;
    if (e < EE) atomicAdd(&g_deg[ei[EE + e]], 1);
}
__global__ void k_dinv() {
    int i = blockIdx.x * blockDim.x + threadIdx.x;
    if (i < NN) g_dinv[i] = rsqrtf((float)g_deg[i] + 1.0f);
}
// single-block scan with smem staging: coalesced in, coalesced out
__global__ void __launch_bounds__(1024) k_scan() {
    extern __shared__ int sd[];            // NN ints (200 KB)
    __shared__ int warp_sums[32];
    __shared__ int warp_excl[32];
    const int tid = threadIdx.x;
    const int lane = tid & 31;
    const int wid = tid >> 5;
    const int ITEMS = (NN + 1023) / 1024;  // 49
    for (int i = tid; i < NN; i += 1024) sd[i] = g_deg[i];
    __syncthreads();
    const int base = tid * ITEMS;
    int s = 0;
    for (int i = 0; i < ITEMS; ++i) {
        int idx = base + i;
        if (idx < NN) s += sd[idx];
    }
    int incl = s;
#pragma unroll
    for (int o = 1; o < 32; o <<= 1) {
        int t = __shfl_up_sync(0xffffffffu, incl, o);
        if (lane >= o) incl += t;
    }
    if (lane == 31) warp_sums[wid] = incl;
    __syncthreads();
    if (wid == 0) {
        int v = warp_sums[lane];
        int iv = v;
#pragma unroll
        for (int o = 1; o < 32; o <<= 1) {
            int t = __shfl_up_sync(0xffffffffu, iv, o);
            if (lane >= o) iv += t;
        }
        warp_excl[lane] = iv - v;
    }
    __syncthreads();
    int excl = warp_excl[wid] + incl - s;
    int run = excl;
    for (int i = 0; i < ITEMS; ++i) {
        int idx = base + i;
        if (idx < NN) {
            int v = sd[idx];
            sd[idx] = run;
            run += v;
        }
    }
    __syncthreads();
    for (int i = tid; i < NN; i += 1024) {
        int v = sd[i];
        g_off[i] = v;
        g_cur[i] = v;
    }
    if (tid == 1023) g_off[NN] = excl + s;
}
__global__ void k_scatter(const int* __restrict__ ei) {
    int e = blockIdx.x * blockDim.x + threadIdx.x;
    if (e >= EE) return;
    int s = ei[e];
    int d = ei[EE + e];
    int pos = atomicAdd(&g_cur[d], 1);
    g_srcs[pos] = s;
    g_coef[pos] = g_dinv[s];
}

// ---------------- input padding / weight conversion (fp32 -> fp16) ------
__global__ void k_pad_x(const float* __restrict__ x) {
    int idx = blockIdx.x * blockDim.x + threadIdx.x;
    if (idx >= NN * KPAD) return;
    int i = idx / KPAD, c = idx % KPAD;
    g_xpad[idx] = (c < 59) ? __float2half_rn(x[i * 59 + c]) : __half(0.0f);
}
__global__ void k_pad_w(const float* __restrict__ w) {
    int idx = blockIdx.x * blockDim.x + threadIdx.x;
    if (idx >= HH * KPAD) return;
    int i = idx / KPAD, c = idx % KPAD;
    g_wpad[idx] = (c < 59) ? __float2half_rn(w[i * 59 + c]) : __half(0.0f);
}
__global__ void k_h16(const float* __restrict__ src, __half* __restrict__ dst,
                      int n) {
    int i = blockIdx.x * blockDim.x + threadIdx.x;
    if (i < n) dst[i] = __float2half_rn(src[i]);
}

// ---------------- fp16 mma.sync GEMM, cp.async double-buffered -----------
// C[M,256] = A[M,K] @ W[256,K]^T (+bias)(+relu), fp16 in / fp16 out,
// fp32 accumulate. 128x128 CTA tile, 256 threads (8 warps 2x4),
// warp tile 64x32, m16n8k16.
#define BKH 32          // K halves per chunk
#define PADH 40         // smem row stride in halves (conflict-free)
#define CHH (128 * PADH)  // halves per operand tile

__global__ void __launch_bounds__(256, 2) gemm_f16_kernel(
    const __half* __restrict__ A, const __half* __restrict__ W,
    const float* __restrict__ bias, __half* __restrict__ C,
    int M, int K, int flags) {
    extern __shared__ __half smh[];   // [A0 | B0 | A1 | B1], CHH halves each
    __shared__ float sBias[128];

    const int tid = threadIdx.x;
    const int wid = tid >> 5;
    const int lane = tid & 31;
    const int m0 = blockIdx.x * 128;
    const int n0 = blockIdx.y * 128;
    const int warp_m = (wid >> 2) * 64;
    const int warp_n = (wid & 3) * 32;

    if (tid < 128) sBias[tid] = (flags & 1) ? bias[n0 + tid] : 0.0f;

    float acc[4][4][4];
#pragma unroll
    for (int mt = 0; mt < 4; ++mt)
#pragma unroll
        for (int nt = 0; nt < 4; ++nt)
#pragma unroll
            for (int r = 0; r < 4; ++r) acc[mt][nt][r] = 0.0f;

    // fill mapping: thread -> row tr, 16 halves at tc
    const int tr = tid >> 1;
    const int tc = (tid & 1) * 16;
    const bool a_valid = (m0 + tr) < M;
    const uint32_t a_sz = a_valid ? 16u : 0u;
    const __half* arow = A + (size_t)(a_valid ? (m0 + tr) : 0) * K + tc;
    const __half* wrow = W + (size_t)(n0 + tr) * K + tc;
    const uint32_t sbase = (uint32_t)__cvta_generic_to_shared(smh);
    const uint32_t sAoff = sbase + (uint32_t)(tr * PADH + tc) * 2u;

    const int lg = lane >> 2;
    const int lt = lane & 3;
    const int nch = K / BKH;

    // prologue: chunk 0 -> buffer 0 (16 B per cp, 2 per operand per thread)
#pragma unroll
    for (int j = 0; j < 2; ++j)
        cp16(sAoff + j * 16u, arow + j * 8, a_sz);
#pragma unroll
    for (int j = 0; j < 2; ++j)
        cp16(sAoff + CHH * 2u + j * 16u, wrow + j * 8, 16u);
    asm volatile("cp.async.commit_group;\n");

    for (int c = 0; c < nch; ++c) {
        if (c + 1 < nch) {
            uint32_t boff = sAoff + ((c + 1) & 1) * (2u * CHH * 2u);
            const __half* ap = arow + (c + 1) * BKH;
            const __half* wp = wrow + (c + 1) * BKH;
#pragma unroll
            for (int j = 0; j < 2; ++j)
                cp16(boff + j * 16u, ap + j * 8, a_sz);
#pragma unroll
            for (int j = 0; j < 2; ++j)
                cp16(boff + CHH * 2u + j * 16u, wp + j * 8, 16u);
            asm volatile("cp.async.commit_group;\n");
            asm volatile("cp.async.wait_group 1;\n");
        } else {
            asm volatile("cp.async.wait_group 0;\n");
        }
        __syncthreads();

        const __half* sA = smh + (c & 1) * (2 * CHH);
        const __half* sB = sA + CHH;
#pragma unroll
        for (int kk = 0; kk < BKH; kk += 16) {
            uint32_t afr[4][4];
            uint32_t bfr[4][2];
#pragma unroll
            for (int mt = 0; mt < 4; ++mt) {
                int ar = warp_m + mt * 16 + lg;
                afr[mt][0] = *(const uint32_t*)&sA[ar * PADH + kk + 2 * lt];
                afr[mt][1] = *(const uint32_t*)&sA[(ar + 8) * PADH + kk + 2 * lt];
                afr[mt][2] = *(const uint32_t*)&sA[ar * PADH + kk + 2 * lt + 8];
                afr[mt][3] = *(const uint32_t*)&sA[(ar + 8) * PADH + kk + 2 * lt + 8];
            }
#pragma unroll
            for (int nt = 0; nt < 4; ++nt) {
                int bn = warp_n + nt * 8 + lg;
                bfr[nt][0] = *(const uint32_t*)&sB[bn * PADH + kk + 2 * lt];
                bfr[nt][1] = *(const uint32_t*)&sB[bn * PADH + kk + 2 * lt + 8];
            }
#pragma unroll
            for (int mt = 0; mt < 4; ++mt) {
#pragma unroll
                for (int nt = 0; nt < 4; ++nt) {
                    asm volatile(
                        "mma.sync.aligned.m16n8k16.row.col.f32.f16.f16.f32 "
                        "{%0,%1,%2,%3}, {%4,%5,%6,%7}, {%8,%9}, {%0,%1,%2,%3};\n"
                        : "+f"(acc[mt][nt][0]), "+f"(acc[mt][nt][1]),
                          "+f"(acc[mt][nt][2]), "+f"(acc[mt][nt][3])
                        : "r"(afr[mt][0]), "r"(afr[mt][1]),
                          "r"(afr[mt][2]), "r"(afr[mt][3]),
                          "r"(bfr[nt][0]), "r"(bfr[nt][1]));
                }
            }
        }
        __syncthreads();
    }

    // epilogue: bias + relu, store half2
    const bool do_relu = (flags & 2) != 0;
#pragma unroll
    for (int mt = 0; mt < 4; ++mt) {
        int r0 = m0 + warp_m + mt * 16 + lg;
        int r1 = r0 + 8;
#pragma unroll
        for (int nt = 0; nt < 4; ++nt) {
            int cl = warp_n + nt * 8 + lt * 2;
            float b0 = sBias[cl], b1 = sBias[cl + 1];
            int col = n0 + cl;
            float v0 = acc[mt][nt][0] + b0;
            float v1 = acc[mt][nt][1] + b1;
            float v2 = acc[mt][nt][2] + b0;
            float v3 = acc[mt][nt][3] + b1;
            if (do_relu) {
                v0 = fmaxf(v0, 0.f); v1 = fmaxf(v1, 0.f);
                v2 = fmaxf(v2, 0.f); v3 = fmaxf(v3, 0.f);
            }
            if (r0 < M)
                *(__half2*)(C + (size_t)r0 * 256 + col) = __floats2half2_rn(v0, v1);
            if (r1 < M)
                *(__half2*)(C + (size_t)r1 * 256 + col) = __floats2half2_rn(v2, v3);
        }
    }
}

// ---------------- GCN aggregation: warp per node, fp16 gather ----------
// out = relu(acc*dinv + dinv^2*self + bias), fp32 accumulate, fp16 out.
__global__ void aggregate_kernel(const __half* __restrict__ h2,
                                 const float* __restrict__ bias,
                                 __half* __restrict__ out) {
    int warp = (blockIdx.x * blockDim.x + threadIdx.x) >> 5;
    if (warp >= NN) return;
    int lane = threadIdx.x & 31;
    const int co = lane * 8;                 // 8 halves per lane
    float acc[8];
#pragma unroll
    for (int i = 0; i < 8; ++i) acc[i] = 0.0f;

    int s = g_off[warp], e = g_off[warp + 1];
    int j = s;
    for (; j + 1 < e; j += 2) {
        int s0 = g_srcs[j], s1 = g_srcs[j + 1];
        float c0 = g_coef[j], c1 = g_coef[j + 1];
        uint4 u0 = *(const uint4*)(h2 + (size_t)s0 * 256 + co);
        uint4 u1 = *(const uint4*)(h2 + (size_t)s1 * 256 + co);
        const __half2* p0 = (const __half2*)&u0;
        const __half2* p1 = (const __half2*)&u1;
#pragma unroll
        for (int q = 0; q < 4; ++q) {
            float2 f0 = __half22float2(p0[q]);
            float2 f1 = __half22float2(p1[q]);
            acc[q * 2 + 0] += c0 * f0.x + c1 * f1.x;
            acc[q * 2 + 1] += c0 * f0.y + c1 * f1.y;
        }
    }
    if (j < e) {
        int s0 = g_srcs[j];
        float c0 = g_coef[j];
        uint4 u0 = *(const uint4*)(h2 + (size_t)s0 * 256 + co);
        const __half2* p0 = (const __half2*)&u0;
#pragma unroll
        for (int q = 0; q < 4; ++q) {
            float2 f0 = __half22float2(p0[q]);
            acc[q * 2 + 0] += c0 * f0.x;
            acc[q * 2 + 1] += c0 * f0.y;
        }
    }

    float di = g_dinv[warp];
    float d2 = di * di;
    uint4 us = *(const uint4*)(h2 + (size_t)warp * 256 + co);
    const __half2* ps = (const __half2*)&us;
    float4 b0 = *(const float4*)(bias + co);
    float4 b1 = *(const float4*)(bias + co + 4);
    const float bb[8] = {b0.x, b0.y, b0.z, b0.w, b1.x, b1.y, b1.z, b1.w};
    __half2 o[4];
#pragma unroll
    for (int q = 0; q < 4; ++q) {
        float2 fs = __half22float2(ps[q]);
        float v0 = fmaxf(acc[q * 2 + 0] * di + d2 * fs.x + bb[q * 2 + 0], 0.0f);
        float v1 = fmaxf(acc[q * 2 + 1] * di + d2 * fs.y + bb[q * 2 + 1], 0.0f);
        o[q] = __floats2half2_rn(v0, v1);
    }
    *(uint4*)(out + (size_t)warp * 256 + co) = *(const uint4*)o;
}

// ---------------- pooling ----------------
__global__ void k_gstart(const int* __restrict__ batch) {
    int i = blockIdx.x * blockDim.x + threadIdx.x;
    if (i >= NN) return;
    int b = batch[i];
    int prev = (i == 0) ? -1 : batch[i - 1];
    for (int g = prev + 1; g <= b; ++g) g_gstart[g] = i;
    if (i == NN - 1) {
        for (int g = b + 1; g <= GG; ++g) g_gstart[g] = NN;
    }
}
__global__ void k_pool(const __half* __restrict__ h, __half* __restrict__ out) {
    int warp = (blockIdx.x * blockDim.x + threadIdx.x) >> 5;
    if (warp >= GG) return;
    int lane = threadIdx.x & 31;
    const int co = lane * 8;
    float acc[8];
#pragma unroll
    for (int i = 0; i < 8; ++i) acc[i] = 0.0f;
    int s = g_gstart[warp], e = g_gstart[warp + 1];
    for (int i = s; i < e; ++i) {
        uint4 u = *(const uint4*)(h + (size_t)i * 256 + co);
        const __half2* p = (const __half2*)&u;
#pragma unroll
        for (int q = 0; q < 4; ++q) {
            float2 f = __half22float2(p[q]);
            acc[q * 2 + 0] += f.x;
            acc[q * 2 + 1] += f.y;
        }
    }
    __half2 o[4];
#pragma unroll
    for (int q = 0; q < 4; ++q)
        o[q] = __floats2half2_rn(acc[q * 2 + 0], acc[q * 2 + 1]);
    *(uint4*)(out + (size_t)warp * 256 + co) = *(const uint4*)o;
}

// ---------------- output head: 2 dots + log_softmax, warp per graph -----
__global__ void k_out(const __half* __restrict__ g,
                      const float* __restrict__ out_w,
                      const float* __restrict__ out_b,
                      float* __restrict__ out) {
    int warp = (blockIdx.x * blockDim.x + threadIdx.x) >> 5;
    if (warp >= GG) return;
    int lane = threadIdx.x & 31;
    const int co = lane * 8;
    uint4 u = *(const uint4*)(g + (size_t)warp * 256 + co);
    const __half2* p = (const __half2*)&u;
    float p0 = 0.f, p1 = 0.f;
#pragma unroll
    for (int q = 0; q < 4; ++q) {
        float2 f = __half22float2(p[q]);
        p0 += f.x * out_w[co + q * 2] + f.y * out_w[co + q * 2 + 1];
        p1 += f.x * out_w[256 + co + q * 2] + f.y * out_w[256 + co + q * 2 + 1];
    }
#pragma unroll
    for (int o = 16; o; o >>= 1) {
        p0 += __shfl_down_sync(0xffffffffu, p0, o);
        p1 += __shfl_down_sync(0xffffffffu, p1, o);
    }
    if (lane == 0) {
        float z0 = p0 + out_b[0];
        float z1 = p1 + out_b[1];
        float m = fmaxf(z0, z1);
        float lse = m + logf(expf(z0 - m) + expf(z1 - m));
        out[warp * 2 + 0] = z0 - lse;
        out[warp * 2 + 1] = z1 - lse;
    }
}

// ---------------- launch ----------------
extern "C" void kernel_launch(void* const* d_in, const int* in_sizes, int n_in,
                              void* d_out, int out_size) {
    const float* x       = (const float*)d_in[0];
    const int*   ei      = (const int*)d_in[1];
    const int*   batch   = (const int*)d_in[2];
    const float* W_embed = (const float*)d_in[3];
    const float* b_embed = (const float*)d_in[4];
    const float* conv_w  = (const float*)d_in[5];
    const float* conv_b  = (const float*)d_in[6];
    const float* fc_w    = (const float*)d_in[7];
    const float* fc_b    = (const float*)d_in[8];
    const float* out_w   = (const float*)d_in[9];
    const float* out_b   = (const float*)d_in[10];
    float* out = (float*)d_out;

    __half *bufA, *bufB, *xpad, *wpad, *wconv, *wfc, *gA, *gB;
    cudaGetSymbolAddress((void**)&bufA, g_bufA);
    cudaGetSymbolAddress((void**)&bufB, g_bufB);
    cudaGetSymbolAddress((void**)&xpad, g_xpad);
    cudaGetSymbolAddress((void**)&wpad, g_wpad);
    cudaGetSymbolAddress((void**)&wconv, g_wconv);
    cudaGetSymbolAddress((void**)&wfc, g_wfc);
    cudaGetSymbolAddress((void**)&gA, g_gA);
    cudaGetSymbolAddress((void**)&gB, g_gB);

    static bool attr_done = false;
    if (!attr_done) {
        cudaFuncSetAttribute(k_scan, cudaFuncAttributeMaxDynamicSharedMemorySize,
                             NN * (int)sizeof(int));
        cudaFuncSetAttribute(gemm_f16_kernel,
                             cudaFuncAttributeMaxDynamicSharedMemorySize,
                             4 * CHH * (int)sizeof(__half));
        attr_done = true;
    }
    const int GEMM_SMEM = 4 * CHH * (int)sizeof(__half);  // 40960

    const int TB = 256;
    // ---- CSR build ----
    k_zero_deg<<<(NN + TB - 1) / TB, TB>>>();
    k_hist<<<(EE + TB - 1) / TB, TB>>>(ei);
    k_dinv<<<(NN + TB - 1) / TB, TB>>>();
    k_scan<<<1, 1024, NN * sizeof(int)>>>();
    k_scatter<<<(EE + TB - 1) / TB, TB>>>(ei);

    // ---- pad/convert inputs & weights to fp16 ----
    k_pad_x<<<(NN * KPAD + TB - 1) / TB, TB>>>(x);
    k_pad_w<<<(HH * KPAD + TB - 1) / TB, TB>>>(W_embed);
    k_h16<<<(3 * HH * HH + TB - 1) / TB, TB>>>(conv_w, wconv, 3 * HH * HH);
    k_h16<<<(3 * HH * HH + TB - 1) / TB, TB>>>(fc_w, wfc, 3 * HH * HH);

    // ---- embed: relu(x @ W_embed^T + b) ----
    dim3 gridN((NN + 127) / 128, 2);
    gemm_f16_kernel<<<gridN, 256, GEMM_SMEM>>>(xpad, wpad, b_embed, bufA,
                                               NN, KPAD, 3);

    // ---- 3 GCN conv layers: gemm A->B, aggregate B->A ----
    for (int i = 0; i < 3; ++i) {
        gemm_f16_kernel<<<gridN, 256, GEMM_SMEM>>>(
            bufA, wconv + (size_t)i * HH * HH, nullptr, bufB, NN, HH, 0);
        aggregate_kernel<<<(NN * 32 + TB - 1) / TB, TB>>>(
            bufB, conv_b + (size_t)i * HH, bufA);
    }

    // ---- global_add_pool ----
    k_gstart<<<(NN + TB - 1) / TB, TB>>>(batch);
    k_pool<<<(GG * 32) / TB, TB>>>(bufA, gA);

    // ---- FC stack ----
    dim3 gridG((GG + 127) / 128, 2);
    gemm_f16_kernel<<<gridG, 256, GEMM_SMEM>>>(gA, wfc, fc_b, gB, GG, HH, 3);
    gemm_f16_kernel<<<gridG, 256, GEMM_SMEM>>>(gB, wfc + HH * HH, fc_b + HH,
                                               gA, GG, HH, 3);
    gemm_f16_kernel<<<gridG, 256, GEMM_SMEM>>>(gA, wfc + 2 * HH * HH,
                                               fc_b + 2 * HH, gB, GG, HH, 3);

    // ---- output + log_softmax ----
    k_out<<<(GG * 32) / TB, TB>>>(gB, out_w, out_b, out);
}

// round 10
// speedup vs baseline: 3.2292x; 1.0862x over previous
#include <cuda_runtime.h>
#include <cuda_fp16.h>
#include <cstdint>

// Problem constants
#define NN 50000
#define EE 800000
#define GG 2048
#define HH 256
#define KPAD 64   // 59 padded to 64

#define SCAN_B 1024
#define SCAN_NB ((NN + SCAN_B - 1) / SCAN_B)   // 49

// ---------------- device scratch (no allocation allowed) ----------------
__device__ __half g_bufA[NN * HH];     // 25.6 MB (activations, fp16)
__device__ __half g_bufB[NN * HH];     // 25.6 MB
__device__ __half g_xpad[NN * KPAD];   // 6.4 MB
__device__ __half g_wpad[HH * KPAD];
__device__ __half g_wconv[3 * HH * HH];
__device__ __half g_wfc[3 * HH * HH];
__device__ int    g_deg[NN];
__device__ int    g_off[NN + 1];
__device__ int    g_cur[NN];
__device__ int    g_bsum[SCAN_NB];
__device__ int    g_srcs[EE];
__device__ float  g_coef[EE];
__device__ float  g_dinv[NN];
__device__ int    g_gstart[GG + 1];
__device__ __half g_gA[GG * HH];
__device__ __half g_gB[GG * HH];

// ---------------- helpers ----------------
__device__ __forceinline__ void cp16(uint32_t dst, const void* src, uint32_t sz) {
    asm volatile("cp.async.cg.shared.global [%0], [%1], 16, %2;\n"
                 :: "r"(dst), "l"(src), "r"(sz));
}

// ---------------- CSR construction ----------------
__global__ void k_zero_deg() {
    int i = blockIdx.x * blockDim.x + threadIdx.x;
    if (i < NN) g_deg[i] = 0;
}
__global__ void k_hist(const int* __restrict__ ei) {
    int e = blockIdx.x * blockDim.x + threadIdx.x;
    if (e < EE) atomicAdd(&g_deg[ei[EE + e]], 1);
}
__global__ void k_dinv() {
    int i = blockIdx.x * blockDim.x + threadIdx.x;
    if (i < NN) g_dinv[i] = rsqrtf((float)g_deg[i] + 1.0f);
}
// ---- multi-block scan: local block scan -> scan of block sums -> add base
__global__ void __launch_bounds__(SCAN_B) k_scan1() {
    __shared__ int ws[32];
    __shared__ int we[32];
    const int t = threadIdx.x;
    const int lane = t & 31;
    const int wid = t >> 5;
    const int idx = blockIdx.x * SCAN_B + t;
    int v = (idx < NN) ? g_deg[idx] : 0;
    int incl = v;
#pragma unroll
    for (int o = 1; o < 32; o <<= 1) {
        int u = __shfl_up_sync(0xffffffffu, incl, o);
        if (lane >= o) incl += u;
    }
    if (lane == 31) ws[wid] = incl;
    __syncthreads();
    if (wid == 0) {
        int s = ws[lane];
        int iv = s;
#pragma unroll
        for (int o = 1; o < 32; o <<= 1) {
            int u = __shfl_up_sync(0xffffffffu, iv, o);
            if (lane >= o) iv += u;
        }
        we[lane] = iv - s;
    }
    __syncthreads();
    int excl = we[wid] + incl - v;
    if (idx < NN) g_off[idx] = excl;
    if (t == SCAN_B - 1) g_bsum[blockIdx.x] = excl + v;
}
__global__ void k_scan2() {
    __shared__ int sh[SCAN_NB];
    int t = threadIdx.x;
    if (t < SCAN_NB) sh[t] = g_bsum[t];
    __syncthreads();
    if (t == 0) {
        int run = 0;
#pragma unroll
        for (int i = 0; i < SCAN_NB; ++i) {
            int v = sh[i];
            sh[i] = run;
            run += v;
        }
        g_off[NN] = run;
    }
    __syncthreads();
    if (t < SCAN_NB) g_bsum[t] = sh[t];
}
__global__ void __launch_bounds__(SCAN_B) k_scan3() {
    int idx = blockIdx.x * SCAN_B + threadIdx.x;
    if (idx < NN) {
        int v = g_off[idx] + g_bsum[blockIdx.x];
        g_off[idx] = v;
        g_cur[idx] = v;
    }
}
__global__ void k_scatter(const int* __restrict__ ei) {
    int e = blockIdx.x * blockDim.x + threadIdx.x;
    if (e >= EE) return;
    int s = ei[e];
    int d = ei[EE + e];
    int pos = atomicAdd(&g_cur[d], 1);
    g_srcs[pos] = s;
    g_coef[pos] = g_dinv[s];
}

// ---------------- input padding / weight conversion (fp32 -> fp16) ------
__global__ void k_pad_x(const float* __restrict__ x) {
    int idx = blockIdx.x * blockDim.x + threadIdx.x;
    if (idx >= NN * KPAD) return;
    int i = idx / KPAD, c = idx % KPAD;
    g_xpad[idx] = (c < 59) ? __float2half_rn(x[i * 59 + c]) : __half(0.0f);
}
__global__ void k_pad_w(const float* __restrict__ w) {
    int idx = blockIdx.x * blockDim.x + threadIdx.x;
    if (idx >= HH * KPAD) return;
    int i = idx / KPAD, c = idx % KPAD;
    g_wpad[idx] = (c < 59) ? __float2half_rn(w[i * 59 + c]) : __half(0.0f);
}
__global__ void k_h16(const float* __restrict__ src, __half* __restrict__ dst,
                      int n) {
    int i = blockIdx.x * blockDim.x + threadIdx.x;
    if (i < n) dst[i] = __float2half_rn(src[i]);
}

// ---------------- fp16 mma.sync GEMM, cp.async double-buffered -----------
// C[M,256] = A[M,K] @ W[256,K]^T (+bias)(+relu), fp16 in / fp16 out,
// fp32 accumulate. 128x128 CTA tile, 256 threads (8 warps 2x4),
// warp tile 64x32, m16n8k16.
#define BKH 32          // K halves per chunk
#define PADH 40         // smem row stride in halves (conflict-free)
#define CHH (128 * PADH)  // halves per operand tile

__global__ void __launch_bounds__(256, 2) gemm_f16_kernel(
    const __half* __restrict__ A, const __half* __restrict__ W,
    const float* __restrict__ bias, __half* __restrict__ C,
    int M, int K, int flags) {
    extern __shared__ __half smh[];   // [A0 | B0 | A1 | B1], CHH halves each
    __shared__ float sBias[128];

    const int tid = threadIdx.x;
    const int wid = tid >> 5;
    const int lane = tid & 31;
    const int m0 = blockIdx.x * 128;
    const int n0 = blockIdx.y * 128;
    const int warp_m = (wid >> 2) * 64;
    const int warp_n = (wid & 3) * 32;

    if (tid < 128) sBias[tid] = (flags & 1) ? bias[n0 + tid] : 0.0f;

    float acc[4][4][4];
#pragma unroll
    for (int mt = 0; mt < 4; ++mt)
#pragma unroll
        for (int nt = 0; nt < 4; ++nt)
#pragma unroll
            for (int r = 0; r < 4; ++r) acc[mt][nt][r] = 0.0f;

    // fill mapping: thread -> row tr, 16 halves at tc
    const int tr = tid >> 1;
    const int tc = (tid & 1) * 16;
    const bool a_valid = (m0 + tr) < M;
    const uint32_t a_sz = a_valid ? 16u : 0u;
    const __half* arow = A + (size_t)(a_valid ? (m0 + tr) : 0) * K + tc;
    const __half* wrow = W + (size_t)(n0 + tr) * K + tc;
    const uint32_t sbase = (uint32_t)__cvta_generic_to_shared(smh);
    const uint32_t sAoff = sbase + (uint32_t)(tr * PADH + tc) * 2u;

    const int lg = lane >> 2;
    const int lt = lane & 3;
    const int nch = K / BKH;

    // prologue: chunk 0 -> buffer 0
#pragma unroll
    for (int j = 0; j < 2; ++j)
        cp16(sAoff + j * 16u, arow + j * 8, a_sz);
#pragma unroll
    for (int j = 0; j < 2; ++j)
        cp16(sAoff + CHH * 2u + j * 16u, wrow + j * 8, 16u);
    asm volatile("cp.async.commit_group;\n");

    for (int c = 0; c < nch; ++c) {
        if (c + 1 < nch) {
            uint32_t boff = sAoff + ((c + 1) & 1) * (2u * CHH * 2u);
            const __half* ap = arow + (c + 1) * BKH;
            const __half* wp = wrow + (c + 1) * BKH;
#pragma unroll
            for (int j = 0; j < 2; ++j)
                cp16(boff + j * 16u, ap + j * 8, a_sz);
#pragma unroll
            for (int j = 0; j < 2; ++j)
                cp16(boff + CHH * 2u + j * 16u, wp + j * 8, 16u);
            asm volatile("cp.async.commit_group;\n");
            asm volatile("cp.async.wait_group 1;\n");
        } else {
            asm volatile("cp.async.wait_group 0;\n");
        }
        __syncthreads();

        const __half* sA = smh + (c & 1) * (2 * CHH);
        const __half* sB = sA + CHH;
#pragma unroll
        for (int kk = 0; kk < BKH; kk += 16) {
            uint32_t afr[4][4];
            uint32_t bfr[4][2];
#pragma unroll
            for (int mt = 0; mt < 4; ++mt) {
                int ar = warp_m + mt * 16 + lg;
                afr[mt][0] = *(const uint32_t*)&sA[ar * PADH + kk + 2 * lt];
                afr[mt][1] = *(const uint32_t*)&sA[(ar + 8) * PADH + kk + 2 * lt];
                afr[mt][2] = *(const uint32_t*)&sA[ar * PADH + kk + 2 * lt + 8];
                afr[mt][3] = *(const uint32_t*)&sA[(ar + 8) * PADH + kk + 2 * lt + 8];
            }
#pragma unroll
            for (int nt = 0; nt < 4; ++nt) {
                int bn = warp_n + nt * 8 + lg;
                bfr[nt][0] = *(const uint32_t*)&sB[bn * PADH + kk + 2 * lt];
                bfr[nt][1] = *(const uint32_t*)&sB[bn * PADH + kk + 2 * lt + 8];
            }
#pragma unroll
            for (int mt = 0; mt < 4; ++mt) {
#pragma unroll
                for (int nt = 0; nt < 4; ++nt) {
                    asm volatile(
                        "mma.sync.aligned.m16n8k16.row.col.f32.f16.f16.f32 "
                        "{%0,%1,%2,%3}, {%4,%5,%6,%7}, {%8,%9}, {%0,%1,%2,%3};\n"
                        : "+f"(acc[mt][nt][0]), "+f"(acc[mt][nt][1]),
                          "+f"(acc[mt][nt][2]), "+f"(acc[mt][nt][3])
                        : "r"(afr[mt][0]), "r"(afr[mt][1]),
                          "r"(afr[mt][2]), "r"(afr[mt][3]),
                          "r"(bfr[nt][0]), "r"(bfr[nt][1]));
                }
            }
        }
        __syncthreads();
    }

    // epilogue: bias + relu, store half2
    const bool do_relu = (flags & 2) != 0;
#pragma unroll
    for (int mt = 0; mt < 4; ++mt) {
        int r0 = m0 + warp_m + mt * 16 + lg;
        int r1 = r0 + 8;
#pragma unroll
        for (int nt = 0; nt < 4; ++nt) {
            int cl = warp_n + nt * 8 + lt * 2;
            float b0 = sBias[cl], b1 = sBias[cl + 1];
            int col = n0 + cl;
            float v0 = acc[mt][nt][0] + b0;
            float v1 = acc[mt][nt][1] + b1;
            float v2 = acc[mt][nt][2] + b0;
            float v3 = acc[mt][nt][3] + b1;
            if (do_relu) {
                v0 = fmaxf(v0, 0.f); v1 = fmaxf(v1, 0.f);
                v2 = fmaxf(v2, 0.f); v3 = fmaxf(v3, 0.f);
            }
            if (r0 < M)
                *(__half2*)(C + (size_t)r0 * 256 + col) = __floats2half2_rn(v0, v1);
            if (r1 < M)
                *(__half2*)(C + (size_t)r1 * 256 + col) = __floats2half2_rn(v2, v3);
        }
    }
}

// ---------------- GCN aggregation: warp per node, fp16 gather ----------
__global__ void aggregate_kernel(const __half* __restrict__ h2,
                                 const float* __restrict__ bias,
                                 __half* __restrict__ out) {
    int warp = (blockIdx.x * blockDim.x + threadIdx.x) >> 5;
    if (warp >= NN) return;
    int lane = threadIdx.x & 31;
    const int co = lane * 8;                 // 8 halves per lane
    float acc[8];
#pragma unroll
    for (int i = 0; i < 8; ++i) acc[i] = 0.0f;

    int s = g_off[warp], e = g_off[warp + 1];
    int j = s;
    for (; j + 1 < e; j += 2) {
        int s0 = g_srcs[j], s1 = g_srcs[j + 1];
        float c0 = g_coef[j], c1 = g_coef[j + 1];
        uint4 u0 = *(const uint4*)(h2 + (size_t)s0 * 256 + co);
        uint4 u1 = *(const uint4*)(h2 + (size_t)s1 * 256 + co);
        const __half2* p0 = (const __half2*)&u0;
        const __half2* p1 = (const __half2*)&u1;
#pragma unroll
        for (int q = 0; q < 4; ++q) {
            float2 f0 = __half22float2(p0[q]);
            float2 f1 = __half22float2(p1[q]);
            acc[q * 2 + 0] += c0 * f0.x + c1 * f1.x;
            acc[q * 2 + 1] += c0 * f0.y + c1 * f1.y;
        }
    }
    if (j < e) {
        int s0 = g_srcs[j];
        float c0 = g_coef[j];
        uint4 u0 = *(const uint4*)(h2 + (size_t)s0 * 256 + co);
        const __half2* p0 = (const __half2*)&u0;
#pragma unroll
        for (int q = 0; q < 4; ++q) {
            float2 f0 = __half22float2(p0[q]);
            acc[q * 2 + 0] += c0 * f0.x;
            acc[q * 2 + 1] += c0 * f0.y;
        }
    }

    float di = g_dinv[warp];
    float d2 = di * di;
    uint4 us = *(const uint4*)(h2 + (size_t)warp * 256 + co);
    const __half2* ps = (const __half2*)&us;
    float4 b0 = *(const float4*)(bias + co);
    float4 b1 = *(const float4*)(bias + co + 4);
    const float bb[8] = {b0.x, b0.y, b0.z, b0.w, b1.x, b1.y, b1.z, b1.w};
    __half2 o[4];
#pragma unroll
    for (int q = 0; q < 4; ++q) {
        float2 fs = __half22float2(ps[q]);
        float v0 = fmaxf(acc[q * 2 + 0] * di + d2 * fs.x + bb[q * 2 + 0], 0.0f);
        float v1 = fmaxf(acc[q * 2 + 1] * di + d2 * fs.y + bb[q * 2 + 1], 0.0f);
        o[q] = __floats2half2_rn(v0, v1);
    }
    *(uint4*)(out + (size_t)warp * 256 + co) = *(const uint4*)o;
}

// ---------------- pooling ----------------
__global__ void k_gstart(const int* __restrict__ batch) {
    int i = blockIdx.x * blockDim.x + threadIdx.x;
    if (i >= NN) return;
    int b = batch[i];
    int prev = (i == 0) ? -1 : batch[i - 1];
    for (int g = prev + 1; g <= b; ++g) g_gstart[g] = i;
    if (i == NN - 1) {
        for (int g = b + 1; g <= GG; ++g) g_gstart[g] = NN;
    }
}
__global__ void k_pool(const __half* __restrict__ h, __half* __restrict__ out) {
    int warp = (blockIdx.x * blockDim.x + threadIdx.x) >> 5;
    if (warp >= GG) return;
    int lane = threadIdx.x & 31;
    const int co = lane * 8;
    float acc[8];
#pragma unroll
    for (int i = 0; i < 8; ++i) acc[i] = 0.0f;
    int s = g_gstart[warp], e = g_gstart[warp + 1];
    for (int i = s; i < e; ++i) {
        uint4 u = *(const uint4*)(h + (size_t)i * 256 + co);
        const __half2* p = (const __half2*)&u;
#pragma unroll
        for (int q = 0; q < 4; ++q) {
            float2 f = __half22float2(p[q]);
            acc[q * 2 + 0] += f.x;
            acc[q * 2 + 1] += f.y;
        }
    }
    __half2 o[4];
#pragma unroll
    for (int q = 0; q < 4; ++q)
        o[q] = __floats2half2_rn(acc[q * 2 + 0], acc[q * 2 + 1]);
    *(uint4*)(out + (size_t)warp * 256 + co) = *(const uint4*)o;
}

// ---------------- output head: 2 dots + log_softmax, warp per graph -----
__global__ void k_out(const __half* __restrict__ g,
                      const float* __restrict__ out_w,
                      const float* __restrict__ out_b,
                      float* __restrict__ out) {
    int warp = (blockIdx.x * blockDim.x + threadIdx.x) >> 5;
    if (warp >= GG) return;
    int lane = threadIdx.x & 31;
    const int co = lane * 8;
    uint4 u = *(const uint4*)(g + (size_t)warp * 256 + co);
    const __half2* p = (const __half2*)&u;
    float p0 = 0.f, p1 = 0.f;
#pragma unroll
    for (int q = 0; q < 4; ++q) {
        float2 f = __half22float2(p[q]);
        p0 += f.x * out_w[co + q * 2] + f.y * out_w[co + q * 2 + 1];
        p1 += f.x * out_w[256 + co + q * 2] + f.y * out_w[256 + co + q * 2 + 1];
    }
#pragma unroll
    for (int o = 16; o; o >>= 1) {
        p0 += __shfl_down_sync(0xffffffffu, p0, o);
        p1 += __shfl_down_sync(0xffffffffu, p1, o);
    }
    if (lane == 0) {
        float z0 = p0 + out_b[0];
        float z1 = p1 + out_b[1];
        float m = fmaxf(z0, z1);
        float lse = m + logf(expf(z0 - m) + expf(z1 - m));
        out[warp * 2 + 0] = z0 - lse;
        out[warp * 2 + 1] = z1 - lse;
    }
}

// ---------------- launch ----------------
extern "C" void kernel_launch(void* const* d_in, const int* in_sizes, int n_in,
                              void* d_out, int out_size) {
    const float* x       = (const float*)d_in[0];
    const int*   ei      = (const int*)d_in[1];
    const int*   batch   = (const int*)d_in[2];
    const float* W_embed = (const float*)d_in[3];
    const float* b_embed = (const float*)d_in[4];
    const float* conv_w  = (const float*)d_in[5];
    const float* conv_b  = (const float*)d_in[6];
    const float* fc_w    = (const float*)d_in[7];
    const float* fc_b    = (const float*)d_in[8];
    const float* out_w   = (const float*)d_in[9];
    const float* out_b   = (const float*)d_in[10];
    float* out = (float*)d_out;

    __half *bufA, *bufB, *xpad, *wpad, *wconv, *wfc, *gA, *gB;
    cudaGetSymbolAddress((void**)&bufA, g_bufA);
    cudaGetSymbolAddress((void**)&bufB, g_bufB);
    cudaGetSymbolAddress((void**)&xpad, g_xpad);
    cudaGetSymbolAddress((void**)&wpad, g_wpad);
    cudaGetSymbolAddress((void**)&wconv, g_wconv);
    cudaGetSymbolAddress((void**)&wfc, g_wfc);
    cudaGetSymbolAddress((void**)&gA, g_gA);
    cudaGetSymbolAddress((void**)&gB, g_gB);

    static bool init_done = false;
    static cudaStream_t s2;
    static cudaEvent_t evFork, evJoin;
    if (!init_done) {
        cudaFuncSetAttribute(gemm_f16_kernel,
                             cudaFuncAttributeMaxDynamicSharedMemorySize,
                             4 * CHH * (int)sizeof(__half));
        cudaStreamCreateWithFlags(&s2, cudaStreamNonBlocking);
        cudaEventCreateWithFlags(&evFork, cudaEventDisableTiming);
        cudaEventCreateWithFlags(&evJoin, cudaEventDisableTiming);
        init_done = true;
    }
    const int GEMM_SMEM = 4 * CHH * (int)sizeof(__half);  // 40960

    const int TB = 256;

    // ---- fork: CSR/index chain on s2, dense chain on default stream ----
    cudaEventRecord(evFork, 0);
    cudaStreamWaitEvent(s2, evFork, 0);

    // s2: CSR build + gstart + fc weight convert
    k_zero_deg<<<(NN + TB - 1) / TB, TB, 0, s2>>>();
    k_hist<<<(EE + TB - 1) / TB, TB, 0, s2>>>(ei);
    k_dinv<<<(NN + TB - 1) / TB, TB, 0, s2>>>();
    k_scan1<<<SCAN_NB, SCAN_B, 0, s2>>>();
    k_scan2<<<1, 64, 0, s2>>>();
    k_scan3<<<SCAN_NB, SCAN_B, 0, s2>>>();
    k_scatter<<<(EE + TB - 1) / TB, TB, 0, s2>>>(ei);
    k_gstart<<<(NN + TB - 1) / TB, TB, 0, s2>>>(batch);
    k_h16<<<(3 * HH * HH + TB - 1) / TB, TB, 0, s2>>>(fc_w, wfc, 3 * HH * HH);

    // default stream: pads/converts + embed GEMM + conv1 GEMM
    k_pad_x<<<(NN * KPAD + TB - 1) / TB, TB>>>(x);
    k_pad_w<<<(HH * KPAD + TB - 1) / TB, TB>>>(W_embed);
    k_h16<<<(3 * HH * HH + TB - 1) / TB, TB>>>(conv_w, wconv, 3 * HH * HH);

    dim3 gridN((NN + 127) / 128, 2);
    gemm_f16_kernel<<<gridN, 256, GEMM_SMEM>>>(xpad, wpad, b_embed, bufA,
                                               NN, KPAD, 3);
    gemm_f16_kernel<<<gridN, 256, GEMM_SMEM>>>(bufA, wconv, nullptr, bufB,
                                               NN, HH, 0);

    // ---- join: aggregate needs CSR ----
    cudaEventRecord(evJoin, s2);
    cudaStreamWaitEvent(0, evJoin, 0);

    aggregate_kernel<<<(NN * 32 + TB - 1) / TB, TB>>>(bufB, conv_b, bufA);
    for (int i = 1; i < 3; ++i) {
        gemm_f16_kernel<<<gridN, 256, GEMM_SMEM>>>(
            bufA, wconv + (size_t)i * HH * HH, nullptr, bufB, NN, HH, 0);
        aggregate_kernel<<<(NN * 32 + TB - 1) / TB, TB>>>(
            bufB, conv_b + (size_t)i * HH, bufA);
    }

    // ---- global_add_pool ----
    k_pool<<<(GG * 32) / TB, TB>>>(bufA, gA);

    // ---- FC stack ----
    dim3 gridG((GG + 127) / 128, 2);
    gemm_f16_kernel<<<gridG, 256, GEMM_SMEM>>>(gA, wfc, fc_b, gB, GG, HH, 3);
    gemm_f16_kernel<<<gridG, 256, GEMM_SMEM>>>(gB, wfc + HH * HH, fc_b + HH,
                                               gA, GG, HH, 3);
    gemm_f16_kernel<<<gridG, 256, GEMM_SMEM>>>(gA, wfc + 2 * HH * HH,
                                               fc_b + 2 * HH, gB, GG, HH, 3);

    // ---- output + log_softmax ----
    k_out<<<(GG * 32) / TB, TB>>>(gB, out_w, out_b, out);
}